// round 12
// baseline (speedup 1.0000x reference)
#include <cuda_runtime.h>
#include <cuda_bf16.h>
#include <cuda_fp16.h>
#include <cstdint>

// Shapes: B=8 T=192 N=64 D=512 H=8 DH=64 C=8
// rows per node = B*T = 1536 ; total token rows = 98304

// ---------------------------------------------------------------------------
// Portable PTX helpers (legal in compute_103 baseline)
// ---------------------------------------------------------------------------
__device__ __forceinline__ uint32_t smem_u32(const void* p) {
    uint32_t a;
    asm("{ .reg .u64 t; cvta.to.shared.u64 t, %1; cvt.u32.u64 %0, t; }"
        : "=r"(a) : "l"(p));
    return a;
}
__device__ __forceinline__ void cpasync16(uint32_t saddr, const void* g) {
    asm volatile("cp.async.cg.shared.global [%0], [%1], 16;"
                 :: "r"(saddr), "l"(g) : "memory");
}
#define CP_COMMIT() asm volatile("cp.async.commit_group;" ::: "memory")
#define CP_WAIT0()  asm volatile("cp.async.wait_group 0;" ::: "memory")
#define CP_WAIT1()  asm volatile("cp.async.wait_group 1;" ::: "memory")

__device__ __forceinline__ void ldsm_x4(uint32_t* r, uint32_t addr) {
    asm volatile("ldmatrix.sync.aligned.m8n8.x4.shared.b16 {%0,%1,%2,%3}, [%4];"
                 : "=r"(r[0]), "=r"(r[1]), "=r"(r[2]), "=r"(r[3]) : "r"(addr));
}
__device__ __forceinline__ void ldsm_x4_t(uint32_t* r, uint32_t addr) {
    asm volatile("ldmatrix.sync.aligned.m8n8.x4.trans.shared.b16 {%0,%1,%2,%3}, [%4];"
                 : "=r"(r[0]), "=r"(r[1]), "=r"(r[2]), "=r"(r[3]) : "r"(addr));
}
__device__ __forceinline__ void mma16816(float* c, const uint32_t* a,
                                         const uint32_t* b) {
    asm volatile(
        "mma.sync.aligned.m16n8k16.row.col.f32.bf16.bf16.f32 "
        "{%0,%1,%2,%3}, {%4,%5,%6,%7}, {%8,%9}, {%0,%1,%2,%3};"
        : "+f"(c[0]), "+f"(c[1]), "+f"(c[2]), "+f"(c[3])
        : "r"(a[0]), "r"(a[1]), "r"(a[2]), "r"(a[3]), "r"(b[0]), "r"(b[1]));
}
__device__ __forceinline__ void mma16816h(float* c, const uint32_t* a,
                                          const uint32_t* b) {
    asm volatile(
        "mma.sync.aligned.m16n8k16.row.col.f32.f16.f16.f32 "
        "{%0,%1,%2,%3}, {%4,%5,%6,%7}, {%8,%9}, {%0,%1,%2,%3};"
        : "+f"(c[0]), "+f"(c[1]), "+f"(c[2]), "+f"(c[3])
        : "r"(a[0]), "r"(a[1]), "r"(a[2]), "r"(a[3]), "r"(b[0]), "r"(b[1]));
}

// GEMM tile smem: 128 rows x 32 halfs (64B/row), 16B-chunk swizzle
__device__ __forceinline__ uint32_t swz(int row, int c16) {
    return (uint32_t)(row * 64 + ((c16 ^ ((row >> 1) & 3)) << 4));
}
// Attention tile smem: rows of 128B (64 bf16/fp16), 8 chunks, swizzle row&7
__device__ __forceinline__ uint32_t swz8(int row, int c16) {
    return (uint32_t)(row * 128 + ((c16 ^ (row & 7)) << 4));
}

// ---------------------------------------------------------------------------
// Scratch (device globals; allocation-free contract)
// ---------------------------------------------------------------------------
static __device__ __half        g_x16[50331648];                  // [B,T,N,D] fp16
static __device__ __nv_bfloat16 g_Qhi[50331648], g_Qlo[50331648]; // [B,N,H,T,DH]
static __device__ __nv_bfloat16 g_Khi[50331648], g_Klo[50331648];
static __device__ __half        g_Vh[50331648];
static __device__ __half        g_O16[50331648];                  // attn out fp16
static __device__ __half g_Wq16h[262144], g_Wq16l[262144];        // [E,D] fp16 split
static __device__ __half g_Wv16h[262144], g_Wv16l[262144];
static __device__ __half g_Pw16h[262144], g_Pw16l[262144];
static __device__ __half g_WkT16h[2097152], g_WkT16l[2097152];    // [C,E,D]
static __device__ int g_cid[64];

// ---------------------------------------------------------------------------
__global__ void cid_kernel(const void* __restrict__ raw) {
    __shared__ int ok;
    int t = threadIdx.x;
    if (t == 0) ok = 1;
    __syncthreads();
    const long long* p64 = (const long long*)raw;
    if (t < 32) {
        long long v = p64[t];
        if (v < 0 || v > 7) atomicExch(&ok, 0);
    }
    __syncthreads();
    if (t < 64) {
        if (ok) g_cid[t] = (int)p64[t];
        else    g_cid[t] = ((const int*)raw)[t];
    }
}

// x: fp32 -> single fp16
__global__ __launch_bounds__(256) void conv_x16(const float* __restrict__ src,
                                                int n4) {
    int i = blockIdx.x * 256 + threadIdx.x;
    if (i >= n4) return;
    float4 v = ((const float4*)src)[i];
    __half2 p0 = __floats2half2_rn(v.x, v.y);
    __half2 p1 = __floats2half2_rn(v.z, v.w);
    uint2 u; u.x = *(uint32_t*)&p0; u.y = *(uint32_t*)&p1;
    *(uint2*)(g_x16 + 4ull * i) = u;
}

// weights: fp32 -> fp16 hi/lo split. which: 1=Wq 2=Wv 3=Pw
__global__ __launch_bounds__(256) void conv_splitw(const float* __restrict__ src,
                                                   int which, int n4) {
    int i = blockIdx.x * 256 + threadIdx.x;
    if (i >= n4) return;
    __half *hi, *lo;
    if (which == 1)      { hi = g_Wq16h; lo = g_Wq16l; }
    else if (which == 2) { hi = g_Wv16h; lo = g_Wv16l; }
    else                 { hi = g_Pw16h; lo = g_Pw16l; }
    float4 v = ((const float4*)src)[i];
    float f[4] = {v.x, v.y, v.z, v.w};
    __half h[4], l[4];
    #pragma unroll
    for (int j = 0; j < 4; j++) {
        h[j] = __float2half_rn(f[j]);
        l[j] = __float2half_rn(f[j] - __half2float(h[j]));
    }
    *(uint2*)(hi + 4ull * i) = *(uint2*)h;
    *(uint2*)(lo + 4ull * i) = *(uint2*)l;
}

// Wk [C,D,E] -> WkT [C,E,D] transposed + fp16 split
__global__ void conv_wkT(const float* __restrict__ Wk) {
    __shared__ float t[32][33];
    int c = blockIdx.z, e0 = blockIdx.x * 32, d0 = blockIdx.y * 32;
    int tx = threadIdx.x, ty = threadIdx.y;
    t[ty][tx] = Wk[((size_t)c * 512 + d0 + ty) * 512 + e0 + tx];
    __syncthreads();
    float v = t[tx][ty];
    size_t o = ((size_t)c * 512 + e0 + ty) * 512 + d0 + tx;
    __half h = __float2half_rn(v);
    g_WkT16h[o] = h;
    g_WkT16l[o] = __float2half_rn(v - __half2float(h));
}

// ---------------------------------------------------------------------------
// fp16 2-pass mma.sync GEMM core: 128x128 tile, 8 warps (2m x 4n),
// acc = A * Bhi^T + A * Blo^T  (A single fp16, B split fp16)
// K=512 in 16 chunks of 32, double-buffered cp.async (2 x 24KB smem)
// stage layout: A@0, Bh@8192, Bl@16384
// __launch_bounds__(256,2): 2 blocks/SM (96KB smem, <=128 regs) so one
// block's mma phase hides the other's sync/load drain.
// ---------------------------------------------------------------------------
#define GEMM_SMEM 49152

__device__ __forceinline__ void load_tile(uint32_t sbase,
        const __half* __restrict__ src, size_t rowStride, int tid) {
    #pragma unroll
    for (int i = 0; i < 2; i++) {
        int idx = tid + i * 256;
        int row = idx >> 2, c16 = idx & 3;
        cpasync16(sbase + swz(row, c16), src + (size_t)row * rowStride + c16 * 8);
    }
}

__device__ __forceinline__ void gemm_core(
        const __half* __restrict__ A, size_t aStride,
        const __half* __restrict__ Bh, const __half* __restrict__ Bl,
        float acc[4][4][4])
{
    extern __shared__ char smem[];
    const uint32_t sb = smem_u32(smem);
    const int tid = threadIdx.x;
    const int wid = tid >> 5, lane = tid & 31;
    const int wm = wid >> 2, wn = wid & 3;

    #pragma unroll
    for (int mt = 0; mt < 4; mt++)
        #pragma unroll
        for (int nt = 0; nt < 4; nt++)
            #pragma unroll
            for (int j = 0; j < 4; j++) acc[mt][nt][j] = 0.f;

    load_tile(sb + 0,     A,  aStride, tid);
    load_tile(sb + 8192,  Bh, 512, tid);
    load_tile(sb + 16384, Bl, 512, tid);
    CP_COMMIT();

    const int lr = lane & 15, lc = lane >> 4;

    for (int c = 0; c < 16; c++) {
        if (c < 15) {
            uint32_t so = sb + ((c + 1) & 1) * 24576;
            int k0 = (c + 1) * 32;
            load_tile(so + 0,     A  + k0, aStride, tid);
            load_tile(so + 8192,  Bh + k0, 512, tid);
            load_tile(so + 16384, Bl + k0, 512, tid);
            CP_COMMIT();
            CP_WAIT1();
        } else {
            CP_WAIT0();
        }
        __syncthreads();

        uint32_t so = sb + (c & 1) * 24576;
        #pragma unroll
        for (int ks = 0; ks < 2; ks++) {
            int c16 = ks * 2 + lc;
            uint32_t af[4][4];
            #pragma unroll
            for (int mt = 0; mt < 4; mt++) {
                int row = wm * 64 + mt * 16 + lr;
                ldsm_x4(af[mt], so + swz(row, c16));
            }
            uint32_t bh[4][2], bl[4][2];
            #pragma unroll
            for (int bt = 0; bt < 2; bt++) {
                int row = wn * 32 + bt * 16 + lr;
                uint32_t o = swz(row, c16);
                uint32_t r[4];
                ldsm_x4(r, so + 8192 + o);
                bh[bt*2][0] = r[0]; bh[bt*2][1] = r[2];
                bh[bt*2+1][0] = r[1]; bh[bt*2+1][1] = r[3];
                ldsm_x4(r, so + 16384 + o);
                bl[bt*2][0] = r[0]; bl[bt*2][1] = r[2];
                bl[bt*2+1][0] = r[1]; bl[bt*2+1][1] = r[3];
            }
            #pragma unroll
            for (int mt = 0; mt < 4; mt++)
                #pragma unroll
                for (int nt = 0; nt < 4; nt++) {
                    mma16816h(acc[mt][nt], af[mt], bh[nt]);
                    mma16816h(acc[mt][nt], af[mt], bl[nt]);
                }
        }
        __syncthreads();
    }
}

// ---------------------------------------------------------------------------
// QKV GEMM: epilogue writes Q,K as split-bf16 (Q pre-scaled 1/8), V as fp16,
// all in [B,N,H,T,DH].
// ---------------------------------------------------------------------------
__global__ __launch_bounds__(256, 2) void qkv_gemm(const float* __restrict__ Wqb,
        const float* __restrict__ Wvb, const float* __restrict__ bk) {
    const int n = blockIdx.z;
    const int row0 = blockIdx.y * 128;
    const int mat = blockIdx.x >> 2;
    const int e0 = (blockIdx.x & 3) * 128;

    const __half *Bh, *Bl; const float* bias;
    if (mat == 0)      { Bh = g_Wq16h + (size_t)e0 * 512; Bl = g_Wq16l + (size_t)e0 * 512;
                         bias = Wqb; }
    else if (mat == 1) { int cid = g_cid[n]; size_t wb = ((size_t)cid * 512 + e0) * 512;
                         Bh = g_WkT16h + wb; Bl = g_WkT16l + wb;
                         bias = bk + cid * 512; }
    else               { Bh = g_Wv16h + (size_t)e0 * 512; Bl = g_Wv16l + (size_t)e0 * 512;
                         bias = Wvb; }

    size_t aoff = ((size_t)row0 * 64 + n) * 512;
    float acc[4][4][4];
    gemm_core(g_x16 + aoff, 32768, Bh, Bl, acc);

    const int tid = threadIdx.x, wid = tid >> 5, lane = tid & 31;
    const int wm = wid >> 2, wn = wid & 3;
    #pragma unroll
    for (int mt = 0; mt < 4; mt++) {
        #pragma unroll
        for (int nt = 0; nt < 4; nt++) {
            int e = e0 + wn * 32 + nt * 8 + 2 * (lane & 3);
            int h = e >> 6, dh0 = e & 63;
            float b0 = bias[e], b1 = bias[e + 1];
            #pragma unroll
            for (int half = 0; half < 2; half++) {
                int r = row0 + wm * 64 + mt * 16 + (lane >> 2) + half * 8;
                int b = r / 192, t = r - b * 192;
                size_t idx = ((((size_t)b * 64 + n) * 8 + h) * 192 + t) * 64 + dh0;
                float v0 = acc[mt][nt][half * 2]     + b0;
                float v1 = acc[mt][nt][half * 2 + 1] + b1;
                if (mat == 0) { v0 *= 0.125f; v1 *= 0.125f; }
                if (mat == 2) {
                    *(__half2*)(g_Vh + idx) = __floats2half2_rn(v0, v1);
                } else {
                    __nv_bfloat162 hp;
                    hp.x = __float2bfloat16(v0);
                    hp.y = __float2bfloat16(v1);
                    __nv_bfloat162 lp;
                    lp.x = __float2bfloat16(v0 - __bfloat162float(hp.x));
                    lp.y = __float2bfloat16(v1 - __bfloat162float(hp.y));
                    if (mat == 0) {
                        *(__nv_bfloat162*)(g_Qhi + idx) = hp;
                        *(__nv_bfloat162*)(g_Qlo + idx) = lp;
                    } else {
                        *(__nv_bfloat162*)(g_Khi + idx) = hp;
                        *(__nv_bfloat162*)(g_Klo + idx) = lp;
                    }
                }
            }
        }
    }
}

// ---------------------------------------------------------------------------
// Output projection GEMM: grid (4 e-tiles, 768 m-tiles) -> d_out fp32
// ---------------------------------------------------------------------------
__global__ __launch_bounds__(256, 2) void proj_gemm(const float* __restrict__ Pb,
                                                    float* __restrict__ out) {
    const int row0 = blockIdx.y * 128;
    const int e0 = blockIdx.x * 128;

    float acc[4][4][4];
    gemm_core(g_O16 + (size_t)row0 * 512, 512,
              g_Pw16h + (size_t)e0 * 512, g_Pw16l + (size_t)e0 * 512, acc);

    const int tid = threadIdx.x, wid = tid >> 5, lane = tid & 31;
    const int wm = wid >> 2, wn = wid & 3;
    #pragma unroll
    for (int mt = 0; mt < 4; mt++) {
        #pragma unroll
        for (int nt = 0; nt < 4; nt++) {
            int e = e0 + wn * 32 + nt * 8 + 2 * (lane & 3);
            float b0 = Pb[e], b1 = Pb[e + 1];
            #pragma unroll
            for (int half = 0; half < 2; half++) {
                int r = row0 + wm * 64 + mt * 16 + (lane >> 2) + half * 8;
                float2 v;
                v.x = acc[mt][nt][half * 2]     + b0;
                v.y = acc[mt][nt][half * 2 + 1] + b1;
                *(float2*)(out + (size_t)r * 512 + e) = v;
            }
        }
    }
}

// ---------------------------------------------------------------------------
// Tensor-core attention: one block per (b,n,h), 8 warps as
// 4 row-groups (wm: 48 rows) x 2 s-halves (wg: 96 cols).
//   S = Q.K^T split-bf16 3-pass ; softmax fp32, Z deferred ; O = E.V fp16
// Output written as single fp16 (g_O16).
// ---------------------------------------------------------------------------
#define SQHI 0
#define SQLO 24576
#define SKHI 49152
#define SKLO 73728
#define SVH  98304
#define SOBUF 122880
#define SPMAX 175104
#define SPSUM 176640
#define ATTN_SMEM 178176

__global__ __launch_bounds__(256, 1) void attn_kernel() {
    extern __shared__ char smc[];
    const uint32_t sb = smem_u32(smc);
    const int bid = blockIdx.x;           // ((b*N+n)*H+h)
    const int h = bid & 7;
    const int n = (bid >> 3) & 63;
    const int b = bid >> 9;
    const int tid = threadIdx.x;
    const int wid = tid >> 5, lane = tid & 31;
    const int wm = wid & 3, wg = wid >> 2;

    const size_t base = (size_t)bid * 12288;   // 192*64

    for (int i = tid; i < 1536; i += 256) {
        int row = i >> 3, c16 = i & 7;
        uint32_t off = swz8(row, c16);
        size_t g = base + (size_t)row * 64 + c16 * 8;
        *(uint4*)(smc + SQHI + off) = *(const uint4*)(g_Qhi + g);
        *(uint4*)(smc + SQLO + off) = *(const uint4*)(g_Qlo + g);
        *(uint4*)(smc + SKHI + off) = *(const uint4*)(g_Khi + g);
        *(uint4*)(smc + SKLO + off) = *(const uint4*)(g_Klo + g);
        *(uint4*)(smc + SVH  + off) = *(const uint4*)(g_Vh  + g);
    }
    __syncthreads();

    // ---- S = Q.K^T (split-bf16 3-pass), warp tile 48 x 96 ----
    float sacc[3][12][4];
    #pragma unroll
    for (int mt = 0; mt < 3; mt++)
        #pragma unroll
        for (int nt = 0; nt < 12; nt++)
            #pragma unroll
            for (int j = 0; j < 4; j++) sacc[mt][nt][j] = 0.f;

    const int lr = lane & 15, lc = lane >> 4;
    #pragma unroll
    for (int kt = 0; kt < 4; kt++) {
        int c16 = kt * 2 + lc;
        uint32_t qh[3][4], ql[3][4];
        #pragma unroll
        for (int mt = 0; mt < 3; mt++) {
            int row = wm * 48 + mt * 16 + lr;
            uint32_t o = swz8(row, c16);
            ldsm_x4(qh[mt], sb + SQHI + o);
            ldsm_x4(ql[mt], sb + SQLO + o);
        }
        uint32_t bh[12][2], bl[12][2];
        #pragma unroll
        for (int ntp = 0; ntp < 6; ntp++) {
            int row = wg * 96 + ntp * 16 + lr;
            uint32_t o = swz8(row, c16);
            uint32_t r4[4];
            ldsm_x4(r4, sb + SKHI + o);
            bh[2*ntp][0] = r4[0]; bh[2*ntp][1] = r4[2];
            bh[2*ntp+1][0] = r4[1]; bh[2*ntp+1][1] = r4[3];
            ldsm_x4(r4, sb + SKLO + o);
            bl[2*ntp][0] = r4[0]; bl[2*ntp][1] = r4[2];
            bl[2*ntp+1][0] = r4[1]; bl[2*ntp+1][1] = r4[3];
        }
        #pragma unroll
        for (int mt = 0; mt < 3; mt++)
            #pragma unroll
            for (int nt = 0; nt < 12; nt++) {
                mma16816(sacc[mt][nt], qh[mt], bh[nt]);
                mma16816(sacc[mt][nt], qh[mt], bl[nt]);
                mma16816(sacc[mt][nt], ql[mt], bh[nt]);
            }
    }

    // ---- softmax: row stats across the two s-half warps ----
    float* pmax = (float*)(smc + SPMAX);
    float* psum = (float*)(smc + SPSUM);
    const int rbase = wm * 48 + (lane >> 2);

    #pragma unroll
    for (int mt = 0; mt < 3; mt++) {
        float m1 = -1e30f, m2 = -1e30f;
        #pragma unroll
        for (int nt = 0; nt < 12; nt++) {
            m1 = fmaxf(m1, fmaxf(sacc[mt][nt][0], sacc[mt][nt][1]));
            m2 = fmaxf(m2, fmaxf(sacc[mt][nt][2], sacc[mt][nt][3]));
        }
        m1 = fmaxf(m1, __shfl_xor_sync(0xffffffffu, m1, 1));
        m1 = fmaxf(m1, __shfl_xor_sync(0xffffffffu, m1, 2));
        m2 = fmaxf(m2, __shfl_xor_sync(0xffffffffu, m2, 1));
        m2 = fmaxf(m2, __shfl_xor_sync(0xffffffffu, m2, 2));
        if ((lane & 3) == 0) {
            pmax[wg * 192 + rbase + mt * 16]     = m1;
            pmax[wg * 192 + rbase + mt * 16 + 8] = m2;
        }
    }
    __syncthreads();

    uint32_t eh[3][6][4];
    #pragma unroll
    for (int mt = 0; mt < 3; mt++) {
        int rr = rbase + mt * 16;
        float gm1 = fmaxf(pmax[rr],     pmax[192 + rr]);
        float gm2 = fmaxf(pmax[rr + 8], pmax[192 + rr + 8]);
        float s1 = 0.f, s2 = 0.f;
        #pragma unroll
        for (int nt = 0; nt < 12; nt++) {
            float c0 = __expf(sacc[mt][nt][0] - gm1);
            float c1 = __expf(sacc[mt][nt][1] - gm1);
            float c2 = __expf(sacc[mt][nt][2] - gm2);
            float c3 = __expf(sacc[mt][nt][3] - gm2);
            sacc[mt][nt][0] = c0; sacc[mt][nt][1] = c1;
            sacc[mt][nt][2] = c2; sacc[mt][nt][3] = c3;
            s1 += c0 + c1; s2 += c2 + c3;
        }
        s1 += __shfl_xor_sync(0xffffffffu, s1, 1);
        s1 += __shfl_xor_sync(0xffffffffu, s1, 2);
        s2 += __shfl_xor_sync(0xffffffffu, s2, 1);
        s2 += __shfl_xor_sync(0xffffffffu, s2, 2);
        if ((lane & 3) == 0) {
            psum[wg * 192 + rr]     = s1;
            psum[wg * 192 + rr + 8] = s2;
        }
        #pragma unroll
        for (int ktp = 0; ktp < 6; ktp++) {
            __half2 p;
            p = __floats2half2_rn(sacc[mt][2*ktp][0],   sacc[mt][2*ktp][1]);
            eh[mt][ktp][0] = *(uint32_t*)&p;
            p = __floats2half2_rn(sacc[mt][2*ktp][2],   sacc[mt][2*ktp][3]);
            eh[mt][ktp][1] = *(uint32_t*)&p;
            p = __floats2half2_rn(sacc[mt][2*ktp+1][0], sacc[mt][2*ktp+1][1]);
            eh[mt][ktp][2] = *(uint32_t*)&p;
            p = __floats2half2_rn(sacc[mt][2*ktp+1][2], sacc[mt][2*ktp+1][3]);
            eh[mt][ktp][3] = *(uint32_t*)&p;
        }
    }
    __syncthreads();

    // ---- O_partial = E.V over this warp's 96 s-columns (fp16 mma) ----
    float oacc[3][8][4];
    #pragma unroll
    for (int mt = 0; mt < 3; mt++)
        #pragma unroll
        for (int nt = 0; nt < 8; nt++)
            #pragma unroll
            for (int j = 0; j < 4; j++) oacc[mt][nt][j] = 0.f;

    const int lg = lane >> 3, lr8 = lane & 7;
    #pragma unroll
    for (int ktp = 0; ktp < 6; ktp++) {
        int s0 = wg * 96 + ktp * 16;
        int vrow = s0 + lr8 + ((lg & 1) << 3);
        uint32_t bv[8][2];
        #pragma unroll
        for (int np = 0; np < 4; np++) {
            int vc = np * 2 + (lg >> 1);
            uint32_t r4[4];
            ldsm_x4_t(r4, sb + SVH + swz8(vrow, vc));
            bv[2*np][0] = r4[0];   bv[2*np][1] = r4[1];
            bv[2*np+1][0] = r4[2]; bv[2*np+1][1] = r4[3];
        }
        #pragma unroll
        for (int mt = 0; mt < 3; mt++)
            #pragma unroll
            for (int nt = 0; nt < 8; nt++)
                mma16816h(oacc[mt][nt], eh[mt][ktp], bv[nt]);
    }

    // ---- combine s-half partials, normalize by Z, write fp16 ----
    float* obuf = (float*)(smc + SOBUF);   // [192][68]
    if (wg == 0) {
        #pragma unroll
        for (int mt = 0; mt < 3; mt++) {
            int rr = rbase + mt * 16;
            #pragma unroll
            for (int nt = 0; nt < 8; nt++) {
                int c = nt * 8 + 2 * (lane & 3);
                *(float2*)&obuf[rr * 68 + c] =
                    make_float2(oacc[mt][nt][0], oacc[mt][nt][1]);
                *(float2*)&obuf[(rr + 8) * 68 + c] =
                    make_float2(oacc[mt][nt][2], oacc[mt][nt][3]);
            }
        }
    }
    __syncthreads();
    if (wg == 1) {
        #pragma unroll
        for (int mt = 0; mt < 3; mt++) {
            int rr = rbase + mt * 16;
            float z1 = 1.0f / (psum[rr] + psum[192 + rr]);
            float z2 = 1.0f / (psum[rr + 8] + psum[192 + rr + 8]);
            #pragma unroll
            for (int nt = 0; nt < 8; nt++) {
                int c = nt * 8 + 2 * (lane & 3);
                float2 p1 = *(float2*)&obuf[rr * 68 + c];
                p1.x = (p1.x + oacc[mt][nt][0]) * z1;
                p1.y = (p1.y + oacc[mt][nt][1]) * z1;
                *(float2*)&obuf[rr * 68 + c] = p1;
                float2 p2 = *(float2*)&obuf[(rr + 8) * 68 + c];
                p2.x = (p2.x + oacc[mt][nt][2]) * z2;
                p2.y = (p2.y + oacc[mt][nt][3]) * z2;
                *(float2*)&obuf[(rr + 8) * 68 + c] = p2;
            }
        }
    }
    __syncthreads();

    // coalesced fp16 writeout to [B,T,N,D]
    const size_t obase = (((size_t)b * 192) * 64 + n) * 512 + h * 64;
    for (int i = tid; i < 3072; i += 256) {
        int row = i >> 4, d = (i & 15) * 4;
        float4 v = *(float4*)&obuf[row * 68 + d];
        __half2 p0 = __floats2half2_rn(v.x, v.y);
        __half2 p1 = __floats2half2_rn(v.z, v.w);
        uint2 u; u.x = *(uint32_t*)&p0; u.y = *(uint32_t*)&p1;
        *(uint2*)(g_O16 + obase + (size_t)row * 32768 + d) = u;
    }
}

// ---------------------------------------------------------------------------
extern "C" void kernel_launch(void* const* d_in, const int* in_sizes, int n_in,
                              void* d_out, int out_size) {
    (void)in_sizes; (void)n_in; (void)out_size;
    const float* x    = (const float*)d_in[0];
    const float* Wq_w = (const float*)d_in[1];
    const float* Wq_b = (const float*)d_in[2];
    const float* Wv_w = (const float*)d_in[3];
    const float* Wv_b = (const float*)d_in[4];
    const float* Wk   = (const float*)d_in[5];
    const float* bk   = (const float*)d_in[6];
    const float* Pw   = (const float*)d_in[7];
    const float* Pb   = (const float*)d_in[8];
    const void*  cid  = d_in[9];
    float* out = (float*)d_out;

    cudaFuncSetAttribute(attn_kernel, cudaFuncAttributeMaxDynamicSharedMemorySize,
                         ATTN_SMEM);
    cudaFuncSetAttribute(qkv_gemm, cudaFuncAttributeMaxDynamicSharedMemorySize,
                         GEMM_SMEM);
    cudaFuncSetAttribute(proj_gemm, cudaFuncAttributeMaxDynamicSharedMemorySize,
                         GEMM_SMEM);

    cid_kernel<<<1, 64>>>(cid);
    conv_x16<<<49152, 256>>>(x, 12582912);
    conv_splitw<<<256, 256>>>(Wq_w, 1, 65536);
    conv_splitw<<<256, 256>>>(Wv_w, 2, 65536);
    conv_splitw<<<256, 256>>>(Pw,   3, 65536);
    conv_wkT<<<dim3(16, 16, 8), dim3(32, 32)>>>(Wk);
    qkv_gemm<<<dim3(12, 12, 64), 256, GEMM_SMEM>>>(Wq_b, Wv_b, bk);
    attn_kernel<<<4096, 256, ATTN_SMEM>>>();
    proj_gemm<<<dim3(4, 768), 256, GEMM_SMEM>>>(Pb, out);
}

// round 13
// speedup vs baseline: 1.0010x; 1.0010x over previous
#include <cuda_runtime.h>
#include <cuda_bf16.h>
#include <cuda_fp16.h>
#include <cstdint>

// Shapes: B=8 T=192 N=64 D=512 H=8 DH=64 C=8
// rows per node = B*T = 1536 ; total token rows = 98304

// ---------------------------------------------------------------------------
// Portable PTX helpers (legal in compute_103 baseline)
// ---------------------------------------------------------------------------
__device__ __forceinline__ uint32_t smem_u32(const void* p) {
    uint32_t a;
    asm("{ .reg .u64 t; cvta.to.shared.u64 t, %1; cvt.u32.u64 %0, t; }"
        : "=r"(a) : "l"(p));
    return a;
}
__device__ __forceinline__ void cpasync16(uint32_t saddr, const void* g) {
    asm volatile("cp.async.cg.shared.global [%0], [%1], 16;"
                 :: "r"(saddr), "l"(g) : "memory");
}
#define CP_COMMIT() asm volatile("cp.async.commit_group;" ::: "memory")
#define CP_WAIT0()  asm volatile("cp.async.wait_group 0;" ::: "memory")
#define CP_WAIT1()  asm volatile("cp.async.wait_group 1;" ::: "memory")

__device__ __forceinline__ void ldsm_x4(uint32_t* r, uint32_t addr) {
    asm volatile("ldmatrix.sync.aligned.m8n8.x4.shared.b16 {%0,%1,%2,%3}, [%4];"
                 : "=r"(r[0]), "=r"(r[1]), "=r"(r[2]), "=r"(r[3]) : "r"(addr));
}
__device__ __forceinline__ void ldsm_x4_t(uint32_t* r, uint32_t addr) {
    asm volatile("ldmatrix.sync.aligned.m8n8.x4.trans.shared.b16 {%0,%1,%2,%3}, [%4];"
                 : "=r"(r[0]), "=r"(r[1]), "=r"(r[2]), "=r"(r[3]) : "r"(addr));
}
__device__ __forceinline__ void mma16816(float* c, const uint32_t* a,
                                         const uint32_t* b) {
    asm volatile(
        "mma.sync.aligned.m16n8k16.row.col.f32.bf16.bf16.f32 "
        "{%0,%1,%2,%3}, {%4,%5,%6,%7}, {%8,%9}, {%0,%1,%2,%3};"
        : "+f"(c[0]), "+f"(c[1]), "+f"(c[2]), "+f"(c[3])
        : "r"(a[0]), "r"(a[1]), "r"(a[2]), "r"(a[3]), "r"(b[0]), "r"(b[1]));
}
__device__ __forceinline__ void mma16816h(float* c, const uint32_t* a,
                                          const uint32_t* b) {
    asm volatile(
        "mma.sync.aligned.m16n8k16.row.col.f32.f16.f16.f32 "
        "{%0,%1,%2,%3}, {%4,%5,%6,%7}, {%8,%9}, {%0,%1,%2,%3};"
        : "+f"(c[0]), "+f"(c[1]), "+f"(c[2]), "+f"(c[3])
        : "r"(a[0]), "r"(a[1]), "r"(a[2]), "r"(a[3]), "r"(b[0]), "r"(b[1]));
}

// GEMM tile smem: 128 rows x 32 halfs (64B/row), 16B-chunk swizzle
__device__ __forceinline__ uint32_t swz(int row, int c16) {
    return (uint32_t)(row * 64 + ((c16 ^ ((row >> 1) & 3)) << 4));
}
// Attention tile smem: rows of 128B (64 bf16/fp16), 8 chunks, swizzle row&7
__device__ __forceinline__ uint32_t swz8(int row, int c16) {
    return (uint32_t)(row * 128 + ((c16 ^ (row & 7)) << 4));
}

// ---------------------------------------------------------------------------
// Scratch (device globals; allocation-free contract)
// ---------------------------------------------------------------------------
static __device__ __half        g_x16[50331648];                  // [B,T,N,D] fp16
static __device__ __nv_bfloat16 g_Qhi[50331648], g_Qlo[50331648]; // [B,N,H,T,DH]
static __device__ __nv_bfloat16 g_Khi[50331648], g_Klo[50331648];
static __device__ __half        g_Vh[50331648];
static __device__ __half        g_O16[50331648];                  // attn out fp16
static __device__ __half g_Wq16h[262144], g_Wq16l[262144];        // [E,D] fp16 split
static __device__ __half g_Wv16h[262144], g_Wv16l[262144];
static __device__ __half g_Pw16h[262144], g_Pw16l[262144];
static __device__ __half g_WkT16h[2097152], g_WkT16l[2097152];    // [C,E,D]
static __device__ int g_cid[64];

// ---------------------------------------------------------------------------
__global__ void cid_kernel(const void* __restrict__ raw) {
    __shared__ int ok;
    int t = threadIdx.x;
    if (t == 0) ok = 1;
    __syncthreads();
    const long long* p64 = (const long long*)raw;
    if (t < 32) {
        long long v = p64[t];
        if (v < 0 || v > 7) atomicExch(&ok, 0);
    }
    __syncthreads();
    if (t < 64) {
        if (ok) g_cid[t] = (int)p64[t];
        else    g_cid[t] = ((const int*)raw)[t];
    }
}

// x: fp32 -> single fp16
__global__ __launch_bounds__(256) void conv_x16(const float* __restrict__ src,
                                                int n4) {
    int i = blockIdx.x * 256 + threadIdx.x;
    if (i >= n4) return;
    float4 v = ((const float4*)src)[i];
    __half2 p0 = __floats2half2_rn(v.x, v.y);
    __half2 p1 = __floats2half2_rn(v.z, v.w);
    uint2 u; u.x = *(uint32_t*)&p0; u.y = *(uint32_t*)&p1;
    *(uint2*)(g_x16 + 4ull * i) = u;
}

// weights: fp32 -> fp16 hi/lo split. which: 1=Wq 2=Wv 3=Pw
__global__ __launch_bounds__(256) void conv_splitw(const float* __restrict__ src,
                                                   int which, int n4) {
    int i = blockIdx.x * 256 + threadIdx.x;
    if (i >= n4) return;
    __half *hi, *lo;
    if (which == 1)      { hi = g_Wq16h; lo = g_Wq16l; }
    else if (which == 2) { hi = g_Wv16h; lo = g_Wv16l; }
    else                 { hi = g_Pw16h; lo = g_Pw16l; }
    float4 v = ((const float4*)src)[i];
    float f[4] = {v.x, v.y, v.z, v.w};
    __half h[4], l[4];
    #pragma unroll
    for (int j = 0; j < 4; j++) {
        h[j] = __float2half_rn(f[j]);
        l[j] = __float2half_rn(f[j] - __half2float(h[j]));
    }
    *(uint2*)(hi + 4ull * i) = *(uint2*)h;
    *(uint2*)(lo + 4ull * i) = *(uint2*)l;
}

// Wk [C,D,E] -> WkT [C,E,D] transposed + fp16 split
__global__ void conv_wkT(const float* __restrict__ Wk) {
    __shared__ float t[32][33];
    int c = blockIdx.z, e0 = blockIdx.x * 32, d0 = blockIdx.y * 32;
    int tx = threadIdx.x, ty = threadIdx.y;
    t[ty][tx] = Wk[((size_t)c * 512 + d0 + ty) * 512 + e0 + tx];
    __syncthreads();
    float v = t[tx][ty];
    size_t o = ((size_t)c * 512 + e0 + ty) * 512 + d0 + tx;
    __half h = __float2half_rn(v);
    g_WkT16h[o] = h;
    g_WkT16l[o] = __float2half_rn(v - __half2float(h));
}

// ---------------------------------------------------------------------------
// fp16 2-pass mma.sync GEMM core: 128x128 tile, 8 warps (2m x 4n),
// acc = A * Bhi^T + A * Blo^T  (A single fp16, B split fp16)
// K=512 in 16 chunks of 32, double-buffered cp.async (2 x 24KB smem)
// stage layout: A@0, Bh@8192, Bl@16384
// mma issued in two separate passes (all bh, then all bl) so consecutive
// mmas never target the same accumulator (reuse distance 16 >> HMMA latency).
// ---------------------------------------------------------------------------
#define GEMM_SMEM 49152

__device__ __forceinline__ void load_tile(uint32_t sbase,
        const __half* __restrict__ src, size_t rowStride, int tid) {
    #pragma unroll
    for (int i = 0; i < 2; i++) {
        int idx = tid + i * 256;
        int row = idx >> 2, c16 = idx & 3;
        cpasync16(sbase + swz(row, c16), src + (size_t)row * rowStride + c16 * 8);
    }
}

__device__ __forceinline__ void gemm_core(
        const __half* __restrict__ A, size_t aStride,
        const __half* __restrict__ Bh, const __half* __restrict__ Bl,
        float acc[4][4][4])
{
    extern __shared__ char smem[];
    const uint32_t sb = smem_u32(smem);
    const int tid = threadIdx.x;
    const int wid = tid >> 5, lane = tid & 31;
    const int wm = wid >> 2, wn = wid & 3;

    #pragma unroll
    for (int mt = 0; mt < 4; mt++)
        #pragma unroll
        for (int nt = 0; nt < 4; nt++)
            #pragma unroll
            for (int j = 0; j < 4; j++) acc[mt][nt][j] = 0.f;

    load_tile(sb + 0,     A,  aStride, tid);
    load_tile(sb + 8192,  Bh, 512, tid);
    load_tile(sb + 16384, Bl, 512, tid);
    CP_COMMIT();

    const int lr = lane & 15, lc = lane >> 4;

    for (int c = 0; c < 16; c++) {
        if (c < 15) {
            uint32_t so = sb + ((c + 1) & 1) * 24576;
            int k0 = (c + 1) * 32;
            load_tile(so + 0,     A  + k0, aStride, tid);
            load_tile(so + 8192,  Bh + k0, 512, tid);
            load_tile(so + 16384, Bl + k0, 512, tid);
            CP_COMMIT();
            CP_WAIT1();
        } else {
            CP_WAIT0();
        }
        __syncthreads();

        uint32_t so = sb + (c & 1) * 24576;
        #pragma unroll
        for (int ks = 0; ks < 2; ks++) {
            int c16 = ks * 2 + lc;
            uint32_t af[4][4];
            #pragma unroll
            for (int mt = 0; mt < 4; mt++) {
                int row = wm * 64 + mt * 16 + lr;
                ldsm_x4(af[mt], so + swz(row, c16));
            }
            uint32_t bh[4][2], bl[4][2];
            #pragma unroll
            for (int bt = 0; bt < 2; bt++) {
                int row = wn * 32 + bt * 16 + lr;
                uint32_t o = swz(row, c16);
                uint32_t r[4];
                ldsm_x4(r, so + 8192 + o);
                bh[bt*2][0] = r[0]; bh[bt*2][1] = r[2];
                bh[bt*2+1][0] = r[1]; bh[bt*2+1][1] = r[3];
                ldsm_x4(r, so + 16384 + o);
                bl[bt*2][0] = r[0]; bl[bt*2][1] = r[2];
                bl[bt*2+1][0] = r[1]; bl[bt*2+1][1] = r[3];
            }
            // pass 1: all tiles vs Bhi  (no back-to-back same-acc mmas)
            #pragma unroll
            for (int mt = 0; mt < 4; mt++)
                #pragma unroll
                for (int nt = 0; nt < 4; nt++)
                    mma16816h(acc[mt][nt], af[mt], bh[nt]);
            // pass 2: all tiles vs Blo
            #pragma unroll
            for (int mt = 0; mt < 4; mt++)
                #pragma unroll
                for (int nt = 0; nt < 4; nt++)
                    mma16816h(acc[mt][nt], af[mt], bl[nt]);
        }
        __syncthreads();
    }
}

// ---------------------------------------------------------------------------
// QKV GEMM: epilogue writes Q,K as split-bf16 (Q pre-scaled 1/8), V as fp16,
// all in [B,N,H,T,DH].
// ---------------------------------------------------------------------------
__global__ __launch_bounds__(256) void qkv_gemm(const float* __restrict__ Wqb,
        const float* __restrict__ Wvb, const float* __restrict__ bk) {
    const int n = blockIdx.z;
    const int row0 = blockIdx.y * 128;
    const int mat = blockIdx.x >> 2;
    const int e0 = (blockIdx.x & 3) * 128;

    const __half *Bh, *Bl; const float* bias;
    if (mat == 0)      { Bh = g_Wq16h + (size_t)e0 * 512; Bl = g_Wq16l + (size_t)e0 * 512;
                         bias = Wqb; }
    else if (mat == 1) { int cid = g_cid[n]; size_t wb = ((size_t)cid * 512 + e0) * 512;
                         Bh = g_WkT16h + wb; Bl = g_WkT16l + wb;
                         bias = bk + cid * 512; }
    else               { Bh = g_Wv16h + (size_t)e0 * 512; Bl = g_Wv16l + (size_t)e0 * 512;
                         bias = Wvb; }

    size_t aoff = ((size_t)row0 * 64 + n) * 512;
    float acc[4][4][4];
    gemm_core(g_x16 + aoff, 32768, Bh, Bl, acc);

    const int tid = threadIdx.x, wid = tid >> 5, lane = tid & 31;
    const int wm = wid >> 2, wn = wid & 3;
    #pragma unroll
    for (int mt = 0; mt < 4; mt++) {
        #pragma unroll
        for (int nt = 0; nt < 4; nt++) {
            int e = e0 + wn * 32 + nt * 8 + 2 * (lane & 3);
            int h = e >> 6, dh0 = e & 63;
            float b0 = bias[e], b1 = bias[e + 1];
            #pragma unroll
            for (int half = 0; half < 2; half++) {
                int r = row0 + wm * 64 + mt * 16 + (lane >> 2) + half * 8;
                int b = r / 192, t = r - b * 192;
                size_t idx = ((((size_t)b * 64 + n) * 8 + h) * 192 + t) * 64 + dh0;
                float v0 = acc[mt][nt][half * 2]     + b0;
                float v1 = acc[mt][nt][half * 2 + 1] + b1;
                if (mat == 0) { v0 *= 0.125f; v1 *= 0.125f; }
                if (mat == 2) {
                    *(__half2*)(g_Vh + idx) = __floats2half2_rn(v0, v1);
                } else {
                    __nv_bfloat162 hp;
                    hp.x = __float2bfloat16(v0);
                    hp.y = __float2bfloat16(v1);
                    __nv_bfloat162 lp;
                    lp.x = __float2bfloat16(v0 - __bfloat162float(hp.x));
                    lp.y = __float2bfloat16(v1 - __bfloat162float(hp.y));
                    if (mat == 0) {
                        *(__nv_bfloat162*)(g_Qhi + idx) = hp;
                        *(__nv_bfloat162*)(g_Qlo + idx) = lp;
                    } else {
                        *(__nv_bfloat162*)(g_Khi + idx) = hp;
                        *(__nv_bfloat162*)(g_Klo + idx) = lp;
                    }
                }
            }
        }
    }
}

// ---------------------------------------------------------------------------
// Output projection GEMM: grid (4 e-tiles, 768 m-tiles) -> d_out fp32
// ---------------------------------------------------------------------------
__global__ __launch_bounds__(256) void proj_gemm(const float* __restrict__ Pb,
                                                 float* __restrict__ out) {
    const int row0 = blockIdx.y * 128;
    const int e0 = blockIdx.x * 128;

    float acc[4][4][4];
    gemm_core(g_O16 + (size_t)row0 * 512, 512,
              g_Pw16h + (size_t)e0 * 512, g_Pw16l + (size_t)e0 * 512, acc);

    const int tid = threadIdx.x, wid = tid >> 5, lane = tid & 31;
    const int wm = wid >> 2, wn = wid & 3;
    #pragma unroll
    for (int mt = 0; mt < 4; mt++) {
        #pragma unroll
        for (int nt = 0; nt < 4; nt++) {
            int e = e0 + wn * 32 + nt * 8 + 2 * (lane & 3);
            float b0 = Pb[e], b1 = Pb[e + 1];
            #pragma unroll
            for (int half = 0; half < 2; half++) {
                int r = row0 + wm * 64 + mt * 16 + (lane >> 2) + half * 8;
                float2 v;
                v.x = acc[mt][nt][half * 2]     + b0;
                v.y = acc[mt][nt][half * 2 + 1] + b1;
                *(float2*)(out + (size_t)r * 512 + e) = v;
            }
        }
    }
}

// ---------------------------------------------------------------------------
// Tensor-core attention: one block per (b,n,h), 8 warps as
// 4 row-groups (wm: 48 rows) x 2 s-halves (wg: 96 cols).
//   S = Q.K^T split-bf16 3-pass ; softmax fp32, Z deferred ; O = E.V fp16
// Score mma issued in 3 separate passes (qh*bh, qh*bl, ql*bh) to avoid
// back-to-back same-accumulator RAW stalls.
// ---------------------------------------------------------------------------
#define SQHI 0
#define SQLO 24576
#define SKHI 49152
#define SKLO 73728
#define SVH  98304
#define SOBUF 122880
#define SPMAX 175104
#define SPSUM 176640
#define ATTN_SMEM 178176

__global__ __launch_bounds__(256, 1) void attn_kernel() {
    extern __shared__ char smc[];
    const uint32_t sb = smem_u32(smc);
    const int bid = blockIdx.x;           // ((b*N+n)*H+h)
    const int h = bid & 7;
    const int n = (bid >> 3) & 63;
    const int b = bid >> 9;
    const int tid = threadIdx.x;
    const int wid = tid >> 5, lane = tid & 31;
    const int wm = wid & 3, wg = wid >> 2;

    const size_t base = (size_t)bid * 12288;   // 192*64

    for (int i = tid; i < 1536; i += 256) {
        int row = i >> 3, c16 = i & 7;
        uint32_t off = swz8(row, c16);
        size_t g = base + (size_t)row * 64 + c16 * 8;
        *(uint4*)(smc + SQHI + off) = *(const uint4*)(g_Qhi + g);
        *(uint4*)(smc + SQLO + off) = *(const uint4*)(g_Qlo + g);
        *(uint4*)(smc + SKHI + off) = *(const uint4*)(g_Khi + g);
        *(uint4*)(smc + SKLO + off) = *(const uint4*)(g_Klo + g);
        *(uint4*)(smc + SVH  + off) = *(const uint4*)(g_Vh  + g);
    }
    __syncthreads();

    // ---- S = Q.K^T (split-bf16 3-pass), warp tile 48 x 96 ----
    float sacc[3][12][4];
    #pragma unroll
    for (int mt = 0; mt < 3; mt++)
        #pragma unroll
        for (int nt = 0; nt < 12; nt++)
            #pragma unroll
            for (int j = 0; j < 4; j++) sacc[mt][nt][j] = 0.f;

    const int lr = lane & 15, lc = lane >> 4;
    #pragma unroll
    for (int kt = 0; kt < 4; kt++) {
        int c16 = kt * 2 + lc;
        uint32_t qh[3][4], ql[3][4];
        #pragma unroll
        for (int mt = 0; mt < 3; mt++) {
            int row = wm * 48 + mt * 16 + lr;
            uint32_t o = swz8(row, c16);
            ldsm_x4(qh[mt], sb + SQHI + o);
            ldsm_x4(ql[mt], sb + SQLO + o);
        }
        uint32_t bh[12][2], bl[12][2];
        #pragma unroll
        for (int ntp = 0; ntp < 6; ntp++) {
            int row = wg * 96 + ntp * 16 + lr;
            uint32_t o = swz8(row, c16);
            uint32_t r4[4];
            ldsm_x4(r4, sb + SKHI + o);
            bh[2*ntp][0] = r4[0]; bh[2*ntp][1] = r4[2];
            bh[2*ntp+1][0] = r4[1]; bh[2*ntp+1][1] = r4[3];
            ldsm_x4(r4, sb + SKLO + o);
            bl[2*ntp][0] = r4[0]; bl[2*ntp][1] = r4[2];
            bl[2*ntp+1][0] = r4[1]; bl[2*ntp+1][1] = r4[3];
        }
        // three separate passes: no consecutive same-acc mmas
        #pragma unroll
        for (int mt = 0; mt < 3; mt++)
            #pragma unroll
            for (int nt = 0; nt < 12; nt++)
                mma16816(sacc[mt][nt], qh[mt], bh[nt]);
        #pragma unroll
        for (int mt = 0; mt < 3; mt++)
            #pragma unroll
            for (int nt = 0; nt < 12; nt++)
                mma16816(sacc[mt][nt], qh[mt], bl[nt]);
        #pragma unroll
        for (int mt = 0; mt < 3; mt++)
            #pragma unroll
            for (int nt = 0; nt < 12; nt++)
                mma16816(sacc[mt][nt], ql[mt], bh[nt]);
    }

    // ---- softmax: row stats across the two s-half warps ----
    float* pmax = (float*)(smc + SPMAX);
    float* psum = (float*)(smc + SPSUM);
    const int rbase = wm * 48 + (lane >> 2);

    #pragma unroll
    for (int mt = 0; mt < 3; mt++) {
        float m1 = -1e30f, m2 = -1e30f;
        #pragma unroll
        for (int nt = 0; nt < 12; nt++) {
            m1 = fmaxf(m1, fmaxf(sacc[mt][nt][0], sacc[mt][nt][1]));
            m2 = fmaxf(m2, fmaxf(sacc[mt][nt][2], sacc[mt][nt][3]));
        }
        m1 = fmaxf(m1, __shfl_xor_sync(0xffffffffu, m1, 1));
        m1 = fmaxf(m1, __shfl_xor_sync(0xffffffffu, m1, 2));
        m2 = fmaxf(m2, __shfl_xor_sync(0xffffffffu, m2, 1));
        m2 = fmaxf(m2, __shfl_xor_sync(0xffffffffu, m2, 2));
        if ((lane & 3) == 0) {
            pmax[wg * 192 + rbase + mt * 16]     = m1;
            pmax[wg * 192 + rbase + mt * 16 + 8] = m2;
        }
    }
    __syncthreads();

    uint32_t eh[3][6][4];
    #pragma unroll
    for (int mt = 0; mt < 3; mt++) {
        int rr = rbase + mt * 16;
        float gm1 = fmaxf(pmax[rr],     pmax[192 + rr]);
        float gm2 = fmaxf(pmax[rr + 8], pmax[192 + rr + 8]);
        float s1 = 0.f, s2 = 0.f;
        #pragma unroll
        for (int nt = 0; nt < 12; nt++) {
            float c0 = __expf(sacc[mt][nt][0] - gm1);
            float c1 = __expf(sacc[mt][nt][1] - gm1);
            float c2 = __expf(sacc[mt][nt][2] - gm2);
            float c3 = __expf(sacc[mt][nt][3] - gm2);
            sacc[mt][nt][0] = c0; sacc[mt][nt][1] = c1;
            sacc[mt][nt][2] = c2; sacc[mt][nt][3] = c3;
            s1 += c0 + c1; s2 += c2 + c3;
        }
        s1 += __shfl_xor_sync(0xffffffffu, s1, 1);
        s1 += __shfl_xor_sync(0xffffffffu, s1, 2);
        s2 += __shfl_xor_sync(0xffffffffu, s2, 1);
        s2 += __shfl_xor_sync(0xffffffffu, s2, 2);
        if ((lane & 3) == 0) {
            psum[wg * 192 + rr]     = s1;
            psum[wg * 192 + rr + 8] = s2;
        }
        #pragma unroll
        for (int ktp = 0; ktp < 6; ktp++) {
            __half2 p;
            p = __floats2half2_rn(sacc[mt][2*ktp][0],   sacc[mt][2*ktp][1]);
            eh[mt][ktp][0] = *(uint32_t*)&p;
            p = __floats2half2_rn(sacc[mt][2*ktp][2],   sacc[mt][2*ktp][3]);
            eh[mt][ktp][1] = *(uint32_t*)&p;
            p = __floats2half2_rn(sacc[mt][2*ktp+1][0], sacc[mt][2*ktp+1][1]);
            eh[mt][ktp][2] = *(uint32_t*)&p;
            p = __floats2half2_rn(sacc[mt][2*ktp+1][2], sacc[mt][2*ktp+1][3]);
            eh[mt][ktp][3] = *(uint32_t*)&p;
        }
    }
    __syncthreads();

    // ---- O_partial = E.V over this warp's 96 s-columns (fp16 mma) ----
    float oacc[3][8][4];
    #pragma unroll
    for (int mt = 0; mt < 3; mt++)
        #pragma unroll
        for (int nt = 0; nt < 8; nt++)
            #pragma unroll
            for (int j = 0; j < 4; j++) oacc[mt][nt][j] = 0.f;

    const int lg = lane >> 3, lr8 = lane & 7;
    #pragma unroll
    for (int ktp = 0; ktp < 6; ktp++) {
        int s0 = wg * 96 + ktp * 16;
        int vrow = s0 + lr8 + ((lg & 1) << 3);
        uint32_t bv[8][2];
        #pragma unroll
        for (int np = 0; np < 4; np++) {
            int vc = np * 2 + (lg >> 1);
            uint32_t r4[4];
            ldsm_x4_t(r4, sb + SVH + swz8(vrow, vc));
            bv[2*np][0] = r4[0];   bv[2*np][1] = r4[1];
            bv[2*np+1][0] = r4[2]; bv[2*np+1][1] = r4[3];
        }
        #pragma unroll
        for (int mt = 0; mt < 3; mt++)
            #pragma unroll
            for (int nt = 0; nt < 8; nt++)
                mma16816h(oacc[mt][nt], eh[mt][ktp], bv[nt]);
    }

    // ---- combine s-half partials, normalize by Z, write fp16 ----
    float* obuf = (float*)(smc + SOBUF);   // [192][68]
    if (wg == 0) {
        #pragma unroll
        for (int mt = 0; mt < 3; mt++) {
            int rr = rbase + mt * 16;
            #pragma unroll
            for (int nt = 0; nt < 8; nt++) {
                int c = nt * 8 + 2 * (lane & 3);
                *(float2*)&obuf[rr * 68 + c] =
                    make_float2(oacc[mt][nt][0], oacc[mt][nt][1]);
                *(float2*)&obuf[(rr + 8) * 68 + c] =
                    make_float2(oacc[mt][nt][2], oacc[mt][nt][3]);
            }
        }
    }
    __syncthreads();
    if (wg == 1) {
        #pragma unroll
        for (int mt = 0; mt < 3; mt++) {
            int rr = rbase + mt * 16;
            float z1 = 1.0f / (psum[rr] + psum[192 + rr]);
            float z2 = 1.0f / (psum[rr + 8] + psum[192 + rr + 8]);
            #pragma unroll
            for (int nt = 0; nt < 8; nt++) {
                int c = nt * 8 + 2 * (lane & 3);
                float2 p1 = *(float2*)&obuf[rr * 68 + c];
                p1.x = (p1.x + oacc[mt][nt][0]) * z1;
                p1.y = (p1.y + oacc[mt][nt][1]) * z1;
                *(float2*)&obuf[rr * 68 + c] = p1;
                float2 p2 = *(float2*)&obuf[(rr + 8) * 68 + c];
                p2.x = (p2.x + oacc[mt][nt][2]) * z2;
                p2.y = (p2.y + oacc[mt][nt][3]) * z2;
                *(float2*)&obuf[(rr + 8) * 68 + c] = p2;
            }
        }
    }
    __syncthreads();

    // coalesced fp16 writeout to [B,T,N,D]
    const size_t obase = (((size_t)b * 192) * 64 + n) * 512 + h * 64;
    for (int i = tid; i < 3072; i += 256) {
        int row = i >> 4, d = (i & 15) * 4;
        float4 v = *(float4*)&obuf[row * 68 + d];
        __half2 p0 = __floats2half2_rn(v.x, v.y);
        __half2 p1 = __floats2half2_rn(v.z, v.w);
        uint2 u; u.x = *(uint32_t*)&p0; u.y = *(uint32_t*)&p1;
        *(uint2*)(g_O16 + obase + (size_t)row * 32768 + d) = u;
    }
}

// ---------------------------------------------------------------------------
extern "C" void kernel_launch(void* const* d_in, const int* in_sizes, int n_in,
                              void* d_out, int out_size) {
    (void)in_sizes; (void)n_in; (void)out_size;
    const float* x    = (const float*)d_in[0];
    const float* Wq_w = (const float*)d_in[1];
    const float* Wq_b = (const float*)d_in[2];
    const float* Wv_w = (const float*)d_in[3];
    const float* Wv_b = (const float*)d_in[4];
    const float* Wk   = (const float*)d_in[5];
    const float* bk   = (const float*)d_in[6];
    const float* Pw   = (const float*)d_in[7];
    const float* Pb   = (const float*)d_in[8];
    const void*  cid  = d_in[9];
    float* out = (float*)d_out;

    cudaFuncSetAttribute(attn_kernel, cudaFuncAttributeMaxDynamicSharedMemorySize,
                         ATTN_SMEM);
    cudaFuncSetAttribute(qkv_gemm, cudaFuncAttributeMaxDynamicSharedMemorySize,
                         GEMM_SMEM);
    cudaFuncSetAttribute(proj_gemm, cudaFuncAttributeMaxDynamicSharedMemorySize,
                         GEMM_SMEM);

    // launch order arranged so qkv_gemm is launch #5 (ncu -s 5 -c 1 target)
    cid_kernel<<<1, 64>>>(cid);                              // 0
    conv_x16<<<49152, 256>>>(x, 12582912);                   // 1
    conv_wkT<<<dim3(16, 16, 8), dim3(32, 32)>>>(Wk);         // 2
    conv_splitw<<<256, 256>>>(Wq_w, 1, 65536);               // 3
    conv_splitw<<<256, 256>>>(Wv_w, 2, 65536);               // 4
    qkv_gemm<<<dim3(12, 12, 64), 256, GEMM_SMEM>>>(Wq_b, Wv_b, bk);  // 5
    attn_kernel<<<4096, 256, ATTN_SMEM>>>();                 // 6
    conv_splitw<<<256, 256>>>(Pw, 3, 65536);                 // 7 (only proj needs it)
    proj_gemm<<<dim3(4, 768), 256, GEMM_SMEM>>>(Pb, out);    // 8
}

// round 16
// speedup vs baseline: 1.2935x; 1.2922x over previous
#include <cuda_runtime.h>
#include <cuda_bf16.h>
#include <cuda_fp16.h>
#include <cstdint>

// Shapes: B=8 T=192 N=64 D=512 H=8 DH=64 C=8
// rows per node = B*T = 1536 ; total token rows = 98304

// ---------------------------------------------------------------------------
// Portable PTX helpers (legal in compute_103 baseline)
// ---------------------------------------------------------------------------
__device__ __forceinline__ uint32_t smem_u32(const void* p) {
    uint32_t a;
    asm("{ .reg .u64 t; cvta.to.shared.u64 t, %1; cvt.u32.u64 %0, t; }"
        : "=r"(a) : "l"(p));
    return a;
}
__device__ __forceinline__ void cpasync16(uint32_t saddr, const void* g) {
    asm volatile("cp.async.cg.shared.global [%0], [%1], 16;"
                 :: "r"(saddr), "l"(g) : "memory");
}
#define CP_COMMIT() asm volatile("cp.async.commit_group;" ::: "memory")
#define CP_WAIT0()  asm volatile("cp.async.wait_group 0;" ::: "memory")
#define CP_WAIT1()  asm volatile("cp.async.wait_group 1;" ::: "memory")

__device__ __forceinline__ void ldsm_x4(uint32_t* r, uint32_t addr) {
    asm volatile("ldmatrix.sync.aligned.m8n8.x4.shared.b16 {%0,%1,%2,%3}, [%4];"
                 : "=r"(r[0]), "=r"(r[1]), "=r"(r[2]), "=r"(r[3]) : "r"(addr));
}
__device__ __forceinline__ void ldsm_x4_t(uint32_t* r, uint32_t addr) {
    asm volatile("ldmatrix.sync.aligned.m8n8.x4.trans.shared.b16 {%0,%1,%2,%3}, [%4];"
                 : "=r"(r[0]), "=r"(r[1]), "=r"(r[2]), "=r"(r[3]) : "r"(addr));
}
__device__ __forceinline__ void mma16816h(float* c, const uint32_t* a,
                                          const uint32_t* b) {
    asm volatile(
        "mma.sync.aligned.m16n8k16.row.col.f32.f16.f16.f32 "
        "{%0,%1,%2,%3}, {%4,%5,%6,%7}, {%8,%9}, {%0,%1,%2,%3};"
        : "+f"(c[0]), "+f"(c[1]), "+f"(c[2]), "+f"(c[3])
        : "r"(a[0]), "r"(a[1]), "r"(a[2]), "r"(a[3]), "r"(b[0]), "r"(b[1]));
}

// GEMM tile smem: 128 rows x 32 halfs (64B/row), 16B-chunk swizzle
__device__ __forceinline__ uint32_t swz(int row, int c16) {
    return (uint32_t)(row * 64 + ((c16 ^ ((row >> 1) & 3)) << 4));
}
// Attention tile smem: rows of 128B (64 fp16), 8 chunks, swizzle row&7
__device__ __forceinline__ uint32_t swz8(int row, int c16) {
    return (uint32_t)(row * 128 + ((c16 ^ (row & 7)) << 4));
}

// ---------------------------------------------------------------------------
// Scratch (device globals; allocation-free contract) — all fp16 single
// ---------------------------------------------------------------------------
static __device__ __half g_x16[50331648];                 // [B,T,N,D]
static __device__ __half g_Q16[50331648];                 // [B,N,H,T,DH] (pre /8)
static __device__ __half g_K16[50331648];
static __device__ __half g_Vh[50331648];
static __device__ __half g_O16[50331648];                 // attn out [B,T,N,D]
static __device__ __half g_Wq16[262144];                  // [E,D]
static __device__ __half g_Wv16[262144];
static __device__ __half g_Pw16[262144];
static __device__ __half g_WkT16[2097152];                // [C,E,D]
static __device__ int g_cid[64];

// ---------------------------------------------------------------------------
__global__ void cid_kernel(const void* __restrict__ raw) {
    __shared__ int ok;
    int t = threadIdx.x;
    if (t == 0) ok = 1;
    __syncthreads();
    const long long* p64 = (const long long*)raw;
    if (t < 32) {
        long long v = p64[t];
        if (v < 0 || v > 7) atomicExch(&ok, 0);
    }
    __syncthreads();
    if (t < 64) {
        if (ok) g_cid[t] = (int)p64[t];
        else    g_cid[t] = ((const int*)raw)[t];
    }
}

// x: fp32 -> fp16
__global__ __launch_bounds__(256) void conv_x16(const float* __restrict__ src,
                                                int n4) {
    int i = blockIdx.x * 256 + threadIdx.x;
    if (i >= n4) return;
    float4 v = ((const float4*)src)[i];
    __half2 p0 = __floats2half2_rn(v.x, v.y);
    __half2 p1 = __floats2half2_rn(v.z, v.w);
    uint2 u; u.x = *(uint32_t*)&p0; u.y = *(uint32_t*)&p1;
    *(uint2*)(g_x16 + 4ull * i) = u;
}

// weights: fp32 -> fp16 single. which: 1=Wq 2=Wv 3=Pw
__global__ __launch_bounds__(256) void conv_w16(const float* __restrict__ src,
                                                int which, int n4) {
    int i = blockIdx.x * 256 + threadIdx.x;
    if (i >= n4) return;
    __half* dst;
    if (which == 1)      dst = g_Wq16;
    else if (which == 2) dst = g_Wv16;
    else                 dst = g_Pw16;
    float4 v = ((const float4*)src)[i];
    __half2 p0 = __floats2half2_rn(v.x, v.y);
    __half2 p1 = __floats2half2_rn(v.z, v.w);
    uint2 u; u.x = *(uint32_t*)&p0; u.y = *(uint32_t*)&p1;
    *(uint2*)(dst + 4ull * i) = u;
}

// Wk [C,D,E] -> WkT [C,E,D] transposed fp16
__global__ void conv_wkT(const float* __restrict__ Wk) {
    __shared__ float t[32][33];
    int c = blockIdx.z, e0 = blockIdx.x * 32, d0 = blockIdx.y * 32;
    int tx = threadIdx.x, ty = threadIdx.y;
    t[ty][tx] = Wk[((size_t)c * 512 + d0 + ty) * 512 + e0 + tx];
    __syncthreads();
    float v = t[tx][ty];
    g_WkT16[((size_t)c * 512 + e0 + ty) * 512 + d0 + tx] = __float2half_rn(v);
}

// ---------------------------------------------------------------------------
// fp16 single-pass mma.sync GEMM core: 128x128 tile, 8 warps (2m x 4n),
// K=512 in 16 chunks of 32, double-buffered cp.async (2 x 16KB smem)
// stage layout: A@0, B@8192
// ---------------------------------------------------------------------------
#define GEMM_SMEM 32768

__device__ __forceinline__ void load_tile(uint32_t sbase,
        const __half* __restrict__ src, size_t rowStride, int tid) {
    #pragma unroll
    for (int i = 0; i < 2; i++) {
        int idx = tid + i * 256;
        int row = idx >> 2, c16 = idx & 3;
        cpasync16(sbase + swz(row, c16), src + (size_t)row * rowStride + c16 * 8);
    }
}

__device__ __forceinline__ void gemm_core(
        const __half* __restrict__ A, size_t aStride,
        const __half* __restrict__ B,
        float acc[4][4][4])
{
    extern __shared__ char smem[];
    const uint32_t sb = smem_u32(smem);
    const int tid = threadIdx.x;
    const int wid = tid >> 5, lane = tid & 31;
    const int wm = wid >> 2, wn = wid & 3;

    #pragma unroll
    for (int mt = 0; mt < 4; mt++)
        #pragma unroll
        for (int nt = 0; nt < 4; nt++)
            #pragma unroll
            for (int j = 0; j < 4; j++) acc[mt][nt][j] = 0.f;

    load_tile(sb + 0,    A, aStride, tid);
    load_tile(sb + 8192, B, 512, tid);
    CP_COMMIT();

    const int lr = lane & 15, lc = lane >> 4;

    for (int c = 0; c < 16; c++) {
        if (c < 15) {
            uint32_t so = sb + ((c + 1) & 1) * 16384;
            int k0 = (c + 1) * 32;
            load_tile(so + 0,    A + k0, aStride, tid);
            load_tile(so + 8192, B + k0, 512, tid);
            CP_COMMIT();
            CP_WAIT1();
        } else {
            CP_WAIT0();
        }
        __syncthreads();

        uint32_t so = sb + (c & 1) * 16384;
        #pragma unroll
        for (int ks = 0; ks < 2; ks++) {
            int c16 = ks * 2 + lc;
            uint32_t af[4][4];
            #pragma unroll
            for (int mt = 0; mt < 4; mt++) {
                int row = wm * 64 + mt * 16 + lr;
                ldsm_x4(af[mt], so + swz(row, c16));
            }
            uint32_t bf[4][2];
            #pragma unroll
            for (int bt = 0; bt < 2; bt++) {
                int row = wn * 32 + bt * 16 + lr;
                uint32_t r[4];
                ldsm_x4(r, so + 8192 + swz(row, c16));
                bf[bt*2][0] = r[0]; bf[bt*2][1] = r[2];
                bf[bt*2+1][0] = r[1]; bf[bt*2+1][1] = r[3];
            }
            #pragma unroll
            for (int mt = 0; mt < 4; mt++)
                #pragma unroll
                for (int nt = 0; nt < 4; nt++)
                    mma16816h(acc[mt][nt], af[mt], bf[nt]);
        }
        __syncthreads();
    }
}

// ---------------------------------------------------------------------------
// QKV GEMM: epilogue writes Q (pre-scaled 1/8), K, V as single fp16
// in [B,N,H,T,DH].
// ---------------------------------------------------------------------------
__global__ __launch_bounds__(256) void qkv_gemm(const float* __restrict__ Wqb,
        const float* __restrict__ Wvb, const float* __restrict__ bk) {
    const int n = blockIdx.z;
    const int row0 = blockIdx.y * 128;
    const int mat = blockIdx.x >> 2;
    const int e0 = (blockIdx.x & 3) * 128;

    const __half* Bw; const float* bias; __half* outArr;
    if (mat == 0)      { Bw = g_Wq16 + (size_t)e0 * 512; bias = Wqb; outArr = g_Q16; }
    else if (mat == 1) { int cid = g_cid[n];
                         Bw = g_WkT16 + ((size_t)cid * 512 + e0) * 512;
                         bias = bk + cid * 512; outArr = g_K16; }
    else               { Bw = g_Wv16 + (size_t)e0 * 512; bias = Wvb; outArr = g_Vh; }

    size_t aoff = ((size_t)row0 * 64 + n) * 512;
    float acc[4][4][4];
    gemm_core(g_x16 + aoff, 32768, Bw, acc);

    const int tid = threadIdx.x, wid = tid >> 5, lane = tid & 31;
    const int wm = wid >> 2, wn = wid & 3;
    #pragma unroll
    for (int mt = 0; mt < 4; mt++) {
        #pragma unroll
        for (int nt = 0; nt < 4; nt++) {
            int e = e0 + wn * 32 + nt * 8 + 2 * (lane & 3);
            int h = e >> 6, dh0 = e & 63;
            float b0 = bias[e], b1 = bias[e + 1];
            #pragma unroll
            for (int half = 0; half < 2; half++) {
                int r = row0 + wm * 64 + mt * 16 + (lane >> 2) + half * 8;
                int b = r / 192, t = r - b * 192;
                size_t idx = ((((size_t)b * 64 + n) * 8 + h) * 192 + t) * 64 + dh0;
                float v0 = acc[mt][nt][half * 2]     + b0;
                float v1 = acc[mt][nt][half * 2 + 1] + b1;
                if (mat == 0) { v0 *= 0.125f; v1 *= 0.125f; }
                *(__half2*)(outArr + idx) = __floats2half2_rn(v0, v1);
            }
        }
    }
}

// ---------------------------------------------------------------------------
// Output projection GEMM: grid (4 e-tiles, 768 m-tiles) -> d_out fp32
// ---------------------------------------------------------------------------
__global__ __launch_bounds__(256) void proj_gemm(const float* __restrict__ Pb,
                                                 float* __restrict__ out) {
    const int row0 = blockIdx.y * 128;
    const int e0 = blockIdx.x * 128;

    float acc[4][4][4];
    gemm_core(g_O16 + (size_t)row0 * 512, 512, g_Pw16 + (size_t)e0 * 512, acc);

    const int tid = threadIdx.x, wid = tid >> 5, lane = tid & 31;
    const int wm = wid >> 2, wn = wid & 3;
    #pragma unroll
    for (int mt = 0; mt < 4; mt++) {
        #pragma unroll
        for (int nt = 0; nt < 4; nt++) {
            int e = e0 + wn * 32 + nt * 8 + 2 * (lane & 3);
            float b0 = Pb[e], b1 = Pb[e + 1];
            #pragma unroll
            for (int half = 0; half < 2; half++) {
                int r = row0 + wm * 64 + mt * 16 + (lane >> 2) + half * 8;
                float2 v;
                v.x = acc[mt][nt][half * 2]     + b0;
                v.y = acc[mt][nt][half * 2 + 1] + b1;
                *(float2*)(out + (size_t)r * 512 + e) = v;
            }
        }
    }
}

// ---------------------------------------------------------------------------
// Tensor-core attention: one block per (b,n,h), 8 warps as
// 4 row-groups (wm: 48 rows) x 2 s-halves (wg: 96 cols).
//   S = Q.K^T single-pass fp16 (Q pre-scaled 1/8)
//   softmax fp32 on fragments, Z deferred ; O = E.V fp16
// smem: Q,K,V fp16 192x64 swizzled + obuf fp32 192x68 + stats
// ---------------------------------------------------------------------------
#define SQ16  0
#define SK16  24576
#define SVH   49152
#define SOBUF 73728
#define SPMAX 125952
#define SPSUM 127488
#define ATTN_SMEM 129024

__global__ __launch_bounds__(256, 1) void attn_kernel() {
    extern __shared__ char smc[];
    const uint32_t sb = smem_u32(smc);
    const int bid = blockIdx.x;           // ((b*N+n)*H+h)
    const int h = bid & 7;
    const int n = (bid >> 3) & 63;
    const int b = bid >> 9;
    const int tid = threadIdx.x;
    const int wid = tid >> 5, lane = tid & 31;
    const int wm = wid & 3, wg = wid >> 2;

    const size_t base = (size_t)bid * 12288;   // 192*64

    for (int i = tid; i < 1536; i += 256) {
        int row = i >> 3, c16 = i & 7;
        uint32_t off = swz8(row, c16);
        size_t g = base + (size_t)row * 64 + c16 * 8;
        *(uint4*)(smc + SQ16 + off) = *(const uint4*)(g_Q16 + g);
        *(uint4*)(smc + SK16 + off) = *(const uint4*)(g_K16 + g);
        *(uint4*)(smc + SVH  + off) = *(const uint4*)(g_Vh  + g);
    }
    __syncthreads();

    // ---- S = Q.K^T (single-pass fp16), warp tile 48 x 96 ----
    float sacc[3][12][4];
    #pragma unroll
    for (int mt = 0; mt < 3; mt++)
        #pragma unroll
        for (int nt = 0; nt < 12; nt++)
            #pragma unroll
            for (int j = 0; j < 4; j++) sacc[mt][nt][j] = 0.f;

    const int lr = lane & 15, lc = lane >> 4;
    #pragma unroll
    for (int kt = 0; kt < 4; kt++) {
        int c16 = kt * 2 + lc;
        uint32_t qf[3][4];
        #pragma unroll
        for (int mt = 0; mt < 3; mt++) {
            int row = wm * 48 + mt * 16 + lr;
            ldsm_x4(qf[mt], sb + SQ16 + swz8(row, c16));
        }
        uint32_t bh[12][2];
        #pragma unroll
        for (int ntp = 0; ntp < 6; ntp++) {
            int row = wg * 96 + ntp * 16 + lr;
            uint32_t r4[4];
            ldsm_x4(r4, sb + SK16 + swz8(row, c16));
            bh[2*ntp][0] = r4[0]; bh[2*ntp][1] = r4[2];
            bh[2*ntp+1][0] = r4[1]; bh[2*ntp+1][1] = r4[3];
        }
        #pragma unroll
        for (int mt = 0; mt < 3; mt++)
            #pragma unroll
            for (int nt = 0; nt < 12; nt++)
                mma16816h(sacc[mt][nt], qf[mt], bh[nt]);
    }

    // ---- softmax: row stats across the two s-half warps ----
    float* pmax = (float*)(smc + SPMAX);
    float* psum = (float*)(smc + SPSUM);
    const int rbase = wm * 48 + (lane >> 2);

    #pragma unroll
    for (int mt = 0; mt < 3; mt++) {
        float m1 = -1e30f, m2 = -1e30f;
        #pragma unroll
        for (int nt = 0; nt < 12; nt++) {
            m1 = fmaxf(m1, fmaxf(sacc[mt][nt][0], sacc[mt][nt][1]));
            m2 = fmaxf(m2, fmaxf(sacc[mt][nt][2], sacc[mt][nt][3]));
        }
        m1 = fmaxf(m1, __shfl_xor_sync(0xffffffffu, m1, 1));
        m1 = fmaxf(m1, __shfl_xor_sync(0xffffffffu, m1, 2));
        m2 = fmaxf(m2, __shfl_xor_sync(0xffffffffu, m2, 1));
        m2 = fmaxf(m2, __shfl_xor_sync(0xffffffffu, m2, 2));
        if ((lane & 3) == 0) {
            pmax[wg * 192 + rbase + mt * 16]     = m1;
            pmax[wg * 192 + rbase + mt * 16 + 8] = m2;
        }
    }
    __syncthreads();

    uint32_t eh[3][6][4];
    #pragma unroll
    for (int mt = 0; mt < 3; mt++) {
        int rr = rbase + mt * 16;
        float gm1 = fmaxf(pmax[rr],     pmax[192 + rr]);
        float gm2 = fmaxf(pmax[rr + 8], pmax[192 + rr + 8]);
        float s1 = 0.f, s2 = 0.f;
        #pragma unroll
        for (int nt = 0; nt < 12; nt++) {
            float c0 = __expf(sacc[mt][nt][0] - gm1);
            float c1 = __expf(sacc[mt][nt][1] - gm1);
            float c2 = __expf(sacc[mt][nt][2] - gm2);
            float c3 = __expf(sacc[mt][nt][3] - gm2);
            sacc[mt][nt][0] = c0; sacc[mt][nt][1] = c1;
            sacc[mt][nt][2] = c2; sacc[mt][nt][3] = c3;
            s1 += c0 + c1; s2 += c2 + c3;
        }
        s1 += __shfl_xor_sync(0xffffffffu, s1, 1);
        s1 += __shfl_xor_sync(0xffffffffu, s1, 2);
        s2 += __shfl_xor_sync(0xffffffffu, s2, 1);
        s2 += __shfl_xor_sync(0xffffffffu, s2, 2);
        if ((lane & 3) == 0) {
            psum[wg * 192 + rr]     = s1;
            psum[wg * 192 + rr + 8] = s2;
        }
        #pragma unroll
        for (int ktp = 0; ktp < 6; ktp++) {
            __half2 p;
            p = __floats2half2_rn(sacc[mt][2*ktp][0],   sacc[mt][2*ktp][1]);
            eh[mt][ktp][0] = *(uint32_t*)&p;
            p = __floats2half2_rn(sacc[mt][2*ktp][2],   sacc[mt][2*ktp][3]);
            eh[mt][ktp][1] = *(uint32_t*)&p;
            p = __floats2half2_rn(sacc[mt][2*ktp+1][0], sacc[mt][2*ktp+1][1]);
            eh[mt][ktp][2] = *(uint32_t*)&p;
            p = __floats2half2_rn(sacc[mt][2*ktp+1][2], sacc[mt][2*ktp+1][3]);
            eh[mt][ktp][3] = *(uint32_t*)&p;
        }
    }
    __syncthreads();

    // ---- O_partial = E.V over this warp's 96 s-columns (fp16 mma) ----
    float oacc[3][8][4];
    #pragma unroll
    for (int mt = 0; mt < 3; mt++)
        #pragma unroll
        for (int nt = 0; nt < 8; nt++)
            #pragma unroll
            for (int j = 0; j < 4; j++) oacc[mt][nt][j] = 0.f;

    const int lg = lane >> 3, lr8 = lane & 7;
    #pragma unroll
    for (int ktp = 0; ktp < 6; ktp++) {
        int s0 = wg * 96 + ktp * 16;
        int vrow = s0 + lr8 + ((lg & 1) << 3);
        uint32_t bv[8][2];
        #pragma unroll
        for (int np = 0; np < 4; np++) {
            int vc = np * 2 + (lg >> 1);
            uint32_t r4[4];
            ldsm_x4_t(r4, sb + SVH + swz8(vrow, vc));
            bv[2*np][0] = r4[0];   bv[2*np][1] = r4[1];
            bv[2*np+1][0] = r4[2]; bv[2*np+1][1] = r4[3];
        }
        #pragma unroll
        for (int mt = 0; mt < 3; mt++)
            #pragma unroll
            for (int nt = 0; nt < 8; nt++)
                mma16816h(oacc[mt][nt], eh[mt][ktp], bv[nt]);
    }

    // ---- combine s-half partials, normalize by Z, write fp16 ----
    float* obuf = (float*)(smc + SOBUF);   // [192][68]
    if (wg == 0) {
        #pragma unroll
        for (int mt = 0; mt < 3; mt++) {
            int rr = rbase + mt * 16;
            #pragma unroll
            for (int nt = 0; nt < 8; nt++) {
                int c = nt * 8 + 2 * (lane & 3);
                *(float2*)&obuf[rr * 68 + c] =
                    make_float2(oacc[mt][nt][0], oacc[mt][nt][1]);
                *(float2*)&obuf[(rr + 8) * 68 + c] =
                    make_float2(oacc[mt][nt][2], oacc[mt][nt][3]);
            }
        }
    }
    __syncthreads();
    if (wg == 1) {
        #pragma unroll
        for (int mt = 0; mt < 3; mt++) {
            int rr = rbase + mt * 16;
            float z1 = 1.0f / (psum[rr] + psum[192 + rr]);
            float z2 = 1.0f / (psum[rr + 8] + psum[192 + rr + 8]);
            #pragma unroll
            for (int nt = 0; nt < 8; nt++) {
                int c = nt * 8 + 2 * (lane & 3);
                float2 p1 = *(float2*)&obuf[rr * 68 + c];
                p1.x = (p1.x + oacc[mt][nt][0]) * z1;
                p1.y = (p1.y + oacc[mt][nt][1]) * z1;
                *(float2*)&obuf[rr * 68 + c] = p1;
                float2 p2 = *(float2*)&obuf[(rr + 8) * 68 + c];
                p2.x = (p2.x + oacc[mt][nt][2]) * z2;
                p2.y = (p2.y + oacc[mt][nt][3]) * z2;
                *(float2*)&obuf[(rr + 8) * 68 + c] = p2;
            }
        }
    }
    __syncthreads();

    // coalesced fp16 writeout to [B,T,N,D]
    const size_t obase = (((size_t)b * 192) * 64 + n) * 512 + h * 64;
    for (int i = tid; i < 3072; i += 256) {
        int row = i >> 4, d = (i & 15) * 4;
        float4 v = *(float4*)&obuf[row * 68 + d];
        __half2 p0 = __floats2half2_rn(v.x, v.y);
        __half2 p1 = __floats2half2_rn(v.z, v.w);
        uint2 u; u.x = *(uint32_t*)&p0; u.y = *(uint32_t*)&p1;
        *(uint2*)(g_O16 + obase + (size_t)row * 32768 + d) = u;
    }
}

// ---------------------------------------------------------------------------
extern "C" void kernel_launch(void* const* d_in, const int* in_sizes, int n_in,
                              void* d_out, int out_size) {
    (void)in_sizes; (void)n_in; (void)out_size;
    const float* x    = (const float*)d_in[0];
    const float* Wq_w = (const float*)d_in[1];
    const float* Wq_b = (const float*)d_in[2];
    const float* Wv_w = (const float*)d_in[3];
    const float* Wv_b = (const float*)d_in[4];
    const float* Wk   = (const float*)d_in[5];
    const float* bk   = (const float*)d_in[6];
    const float* Pw   = (const float*)d_in[7];
    const float* Pb   = (const float*)d_in[8];
    const void*  cid  = d_in[9];
    float* out = (float*)d_out;

    cudaFuncSetAttribute(attn_kernel, cudaFuncAttributeMaxDynamicSharedMemorySize,
                         ATTN_SMEM);
    cudaFuncSetAttribute(qkv_gemm, cudaFuncAttributeMaxDynamicSharedMemorySize,
                         GEMM_SMEM);
    cudaFuncSetAttribute(proj_gemm, cudaFuncAttributeMaxDynamicSharedMemorySize,
                         GEMM_SMEM);

    cid_kernel<<<1, 64>>>(cid);
    conv_x16<<<49152, 256>>>(x, 12582912);
    conv_wkT<<<dim3(16, 16, 8), dim3(32, 32)>>>(Wk);
    conv_w16<<<256, 256>>>(Wq_w, 1, 65536);
    conv_w16<<<256, 256>>>(Wv_w, 2, 65536);
    qkv_gemm<<<dim3(12, 12, 64), 256, GEMM_SMEM>>>(Wq_b, Wv_b, bk);
    attn_kernel<<<4096, 256, ATTN_SMEM>>>();
    conv_w16<<<256, 256>>>(Pw, 3, 65536);
    proj_gemm<<<dim3(4, 768), 256, GEMM_SMEM>>>(Pb, out);
}

// round 17
// speedup vs baseline: 1.6199x; 1.2523x over previous
#include <cuda_runtime.h>
#include <cuda_bf16.h>
#include <cuda_fp16.h>
#include <cstdint>

// Shapes: B=8 T=192 N=64 D=512 H=8 DH=64 C=8
// rows per node = B*T = 1536 ; total token rows = 98304

// ---------------------------------------------------------------------------
// Portable PTX helpers (legal in compute_103 baseline)
// ---------------------------------------------------------------------------
__device__ __forceinline__ uint32_t smem_u32(const void* p) {
    uint32_t a;
    asm("{ .reg .u64 t; cvta.to.shared.u64 t, %1; cvt.u32.u64 %0, t; }"
        : "=r"(a) : "l"(p));
    return a;
}
__device__ __forceinline__ void cpasync16(uint32_t saddr, const void* g) {
    asm volatile("cp.async.cg.shared.global [%0], [%1], 16;"
                 :: "r"(saddr), "l"(g) : "memory");
}
#define CP_COMMIT() asm volatile("cp.async.commit_group;" ::: "memory")
#define CP_WAIT0()  asm volatile("cp.async.wait_group 0;" ::: "memory")
#define CP_WAIT1()  asm volatile("cp.async.wait_group 1;" ::: "memory")

__device__ __forceinline__ void ldsm_x4(uint32_t* r, uint32_t addr) {
    asm volatile("ldmatrix.sync.aligned.m8n8.x4.shared.b16 {%0,%1,%2,%3}, [%4];"
                 : "=r"(r[0]), "=r"(r[1]), "=r"(r[2]), "=r"(r[3]) : "r"(addr));
}
__device__ __forceinline__ void ldsm_x4_t(uint32_t* r, uint32_t addr) {
    asm volatile("ldmatrix.sync.aligned.m8n8.x4.trans.shared.b16 {%0,%1,%2,%3}, [%4];"
                 : "=r"(r[0]), "=r"(r[1]), "=r"(r[2]), "=r"(r[3]) : "r"(addr));
}
__device__ __forceinline__ void mma16816h(float* c, const uint32_t* a,
                                          const uint32_t* b) {
    asm volatile(
        "mma.sync.aligned.m16n8k16.row.col.f32.f16.f16.f32 "
        "{%0,%1,%2,%3}, {%4,%5,%6,%7}, {%8,%9}, {%0,%1,%2,%3};"
        : "+f"(c[0]), "+f"(c[1]), "+f"(c[2]), "+f"(c[3])
        : "r"(a[0]), "r"(a[1]), "r"(a[2]), "r"(a[3]), "r"(b[0]), "r"(b[1]));
}

// 128B-row tile swizzle (64 fp16/row, 8 x 16B chunks): conflict-free for
// cp.async 16B stores and all ldmatrix phases. Used by GEMM + attention.
__device__ __forceinline__ uint32_t swz8(int row, int c16) {
    return (uint32_t)(row * 128 + ((c16 ^ (row & 7)) << 4));
}

// ---------------------------------------------------------------------------
// Scratch (device globals; allocation-free contract) — all fp16 single
// ---------------------------------------------------------------------------
static __device__ __half g_x16[50331648];                 // [B,T,N,D]
static __device__ __half g_Q16[50331648];                 // [B,N,H,T,DH] (pre /8)
static __device__ __half g_K16[50331648];
static __device__ __half g_Vh[50331648];
static __device__ __half g_O16[50331648];                 // attn out [B,T,N,D]
static __device__ __half g_Wq16[262144];                  // [E,D]
static __device__ __half g_Wv16[262144];
static __device__ __half g_Pw16[262144];
static __device__ __half g_WkT16[2097152];                // [C,E,D]
static __device__ int g_cid[64];

// ---------------------------------------------------------------------------
__global__ void cid_kernel(const void* __restrict__ raw) {
    __shared__ int ok;
    int t = threadIdx.x;
    if (t == 0) ok = 1;
    __syncthreads();
    const long long* p64 = (const long long*)raw;
    if (t < 32) {
        long long v = p64[t];
        if (v < 0 || v > 7) atomicExch(&ok, 0);
    }
    __syncthreads();
    if (t < 64) {
        if (ok) g_cid[t] = (int)p64[t];
        else    g_cid[t] = ((const int*)raw)[t];
    }
}

// x: fp32 -> fp16
__global__ __launch_bounds__(256) void conv_x16(const float* __restrict__ src,
                                                int n4) {
    int i = blockIdx.x * 256 + threadIdx.x;
    if (i >= n4) return;
    float4 v = ((const float4*)src)[i];
    __half2 p0 = __floats2half2_rn(v.x, v.y);
    __half2 p1 = __floats2half2_rn(v.z, v.w);
    uint2 u; u.x = *(uint32_t*)&p0; u.y = *(uint32_t*)&p1;
    *(uint2*)(g_x16 + 4ull * i) = u;
}

// weights: fp32 -> fp16 single. which: 1=Wq 2=Wv 3=Pw
__global__ __launch_bounds__(256) void conv_w16(const float* __restrict__ src,
                                                int which, int n4) {
    int i = blockIdx.x * 256 + threadIdx.x;
    if (i >= n4) return;
    __half* dst;
    if (which == 1)      dst = g_Wq16;
    else if (which == 2) dst = g_Wv16;
    else                 dst = g_Pw16;
    float4 v = ((const float4*)src)[i];
    __half2 p0 = __floats2half2_rn(v.x, v.y);
    __half2 p1 = __floats2half2_rn(v.z, v.w);
    uint2 u; u.x = *(uint32_t*)&p0; u.y = *(uint32_t*)&p1;
    *(uint2*)(dst + 4ull * i) = u;
}

// Wk [C,D,E] -> WkT [C,E,D] transposed fp16
__global__ void conv_wkT(const float* __restrict__ Wk) {
    __shared__ float t[32][33];
    int c = blockIdx.z, e0 = blockIdx.x * 32, d0 = blockIdx.y * 32;
    int tx = threadIdx.x, ty = threadIdx.y;
    t[ty][tx] = Wk[((size_t)c * 512 + d0 + ty) * 512 + e0 + tx];
    __syncthreads();
    float v = t[tx][ty];
    g_WkT16[((size_t)c * 512 + e0 + ty) * 512 + d0 + tx] = __float2half_rn(v);
}

// ---------------------------------------------------------------------------
// fp16 mma.sync GEMM core: 128x128 tile, 8 warps (2m x 4n),
// K=512 in 8 chunks of 64, double-buffered cp.async (2 x 32KB smem).
// stage layout: A@0 (16KB), B@16384 (16KB). Half the syncs of the K32 core.
// ---------------------------------------------------------------------------
#define GEMM_SMEM 65536

__device__ __forceinline__ void load_tile64(uint32_t sbase,
        const __half* __restrict__ src, size_t rowStride, int tid) {
    // 128 rows x 128B : 1024 16B-chunks, 4 per thread
    #pragma unroll
    for (int i = 0; i < 4; i++) {
        int idx = tid + i * 256;
        int row = idx >> 3, c16 = idx & 7;
        cpasync16(sbase + swz8(row, c16), src + (size_t)row * rowStride + c16 * 8);
    }
}

__device__ __forceinline__ void gemm_core(
        const __half* __restrict__ A, size_t aStride,
        const __half* __restrict__ B,
        float acc[4][4][4])
{
    extern __shared__ char smem[];
    const uint32_t sb = smem_u32(smem);
    const int tid = threadIdx.x;
    const int wid = tid >> 5, lane = tid & 31;
    const int wm = wid >> 2, wn = wid & 3;

    #pragma unroll
    for (int mt = 0; mt < 4; mt++)
        #pragma unroll
        for (int nt = 0; nt < 4; nt++)
            #pragma unroll
            for (int j = 0; j < 4; j++) acc[mt][nt][j] = 0.f;

    load_tile64(sb + 0,     A, aStride, tid);
    load_tile64(sb + 16384, B, 512, tid);
    CP_COMMIT();

    const int lr = lane & 15, lc = lane >> 4;

    for (int c = 0; c < 8; c++) {
        if (c < 7) {
            uint32_t so = sb + ((c + 1) & 1) * 32768;
            int k0 = (c + 1) * 64;
            load_tile64(so + 0,     A + k0, aStride, tid);
            load_tile64(so + 16384, B + k0, 512, tid);
            CP_COMMIT();
            CP_WAIT1();
        } else {
            CP_WAIT0();
        }
        __syncthreads();

        uint32_t so = sb + (c & 1) * 32768;
        #pragma unroll
        for (int ks = 0; ks < 4; ks++) {
            int c16 = ks * 2 + lc;
            uint32_t af[4][4];
            #pragma unroll
            for (int mt = 0; mt < 4; mt++) {
                int row = wm * 64 + mt * 16 + lr;
                ldsm_x4(af[mt], so + swz8(row, c16));
            }
            uint32_t bf[4][2];
            #pragma unroll
            for (int bt = 0; bt < 2; bt++) {
                int row = wn * 32 + bt * 16 + lr;
                uint32_t r[4];
                ldsm_x4(r, so + 16384 + swz8(row, c16));
                bf[bt*2][0] = r[0]; bf[bt*2][1] = r[2];
                bf[bt*2+1][0] = r[1]; bf[bt*2+1][1] = r[3];
            }
            #pragma unroll
            for (int mt = 0; mt < 4; mt++)
                #pragma unroll
                for (int nt = 0; nt < 4; nt++)
                    mma16816h(acc[mt][nt], af[mt], bf[nt]);
        }
        __syncthreads();
    }
}

// ---------------------------------------------------------------------------
// QKV GEMM: epilogue stages the tile in smem (free after the mainloop) and
// writes full 128B rows coalesced into [B,N,H,T,DH] fp16.
// smem staging: 128 rows x 136-half pitch (272B) -> conflict-free phases.
// ---------------------------------------------------------------------------
#define ST_PITCH 136

__global__ __launch_bounds__(256) void qkv_gemm(const float* __restrict__ Wqb,
        const float* __restrict__ Wvb, const float* __restrict__ bk) {
    const int n = blockIdx.z;
    const int row0 = blockIdx.y * 128;
    const int mat = blockIdx.x >> 2;
    const int e0 = (blockIdx.x & 3) * 128;

    const __half* Bw; const float* bias; __half* outArr;
    if (mat == 0)      { Bw = g_Wq16 + (size_t)e0 * 512; bias = Wqb; outArr = g_Q16; }
    else if (mat == 1) { int cid = g_cid[n];
                         Bw = g_WkT16 + ((size_t)cid * 512 + e0) * 512;
                         bias = bk + cid * 512; outArr = g_K16; }
    else               { Bw = g_Wv16 + (size_t)e0 * 512; bias = Wvb; outArr = g_Vh; }

    size_t aoff = ((size_t)row0 * 64 + n) * 512;
    float acc[4][4][4];
    gemm_core(g_x16 + aoff, 32768, Bw, acc);

    extern __shared__ char smem[];
    __half* st = (__half*)smem;
    const int tid = threadIdx.x, wid = tid >> 5, lane = tid & 31;
    const int wm = wid >> 2, wn = wid & 3;
    const float qscale = (mat == 0) ? 0.125f : 1.0f;

    // stage acc (+bias, Q scale) into smem
    #pragma unroll
    for (int mt = 0; mt < 4; mt++) {
        #pragma unroll
        for (int nt = 0; nt < 4; nt++) {
            int ecol = wn * 32 + nt * 8 + 2 * (lane & 3);
            float b0 = bias[e0 + ecol], b1 = bias[e0 + ecol + 1];
            #pragma unroll
            for (int half = 0; half < 2; half++) {
                int r = wm * 64 + mt * 16 + (lane >> 2) + half * 8;
                float v0 = (acc[mt][nt][half * 2]     + b0) * qscale;
                float v1 = (acc[mt][nt][half * 2 + 1] + b1) * qscale;
                *(__half2*)&st[r * ST_PITCH + ecol] = __floats2half2_rn(v0, v1);
            }
        }
    }
    __syncthreads();

    // coalesced write: 2048 uint4 (128 rows x 2 heads x 8 x 16B)
    #pragma unroll
    for (int i = 0; i < 8; i++) {
        int idx = tid + i * 256;
        int r = idx >> 4;            // 16 uint4 per row
        int seg = idx & 15;
        int hh = seg >> 3, s8 = seg & 7;
        int rr = row0 + r;
        int b = rr / 192, t = rr - b * 192;
        int h = (e0 >> 6) + hh;
        uint4 v = *(uint4*)&st[r * ST_PITCH + hh * 64 + s8 * 8];
        *(uint4*)(outArr + ((((size_t)b * 64 + n) * 8 + h) * 192 + t) * 64 + s8 * 8) = v;
    }
}

// ---------------------------------------------------------------------------
// Output projection GEMM: grid (4 e-tiles, 768 m-tiles) -> d_out fp32
// (fp32 float2 stores already land in fully-written 32B sectors)
// ---------------------------------------------------------------------------
__global__ __launch_bounds__(256) void proj_gemm(const float* __restrict__ Pb,
                                                 float* __restrict__ out) {
    const int row0 = blockIdx.y * 128;
    const int e0 = blockIdx.x * 128;

    float acc[4][4][4];
    gemm_core(g_O16 + (size_t)row0 * 512, 512, g_Pw16 + (size_t)e0 * 512, acc);

    const int tid = threadIdx.x, wid = tid >> 5, lane = tid & 31;
    const int wm = wid >> 2, wn = wid & 3;
    #pragma unroll
    for (int mt = 0; mt < 4; mt++) {
        #pragma unroll
        for (int nt = 0; nt < 4; nt++) {
            int e = e0 + wn * 32 + nt * 8 + 2 * (lane & 3);
            float b0 = Pb[e], b1 = Pb[e + 1];
            #pragma unroll
            for (int half = 0; half < 2; half++) {
                int r = row0 + wm * 64 + mt * 16 + (lane >> 2) + half * 8;
                float2 v;
                v.x = acc[mt][nt][half * 2]     + b0;
                v.y = acc[mt][nt][half * 2 + 1] + b1;
                *(float2*)(out + (size_t)r * 512 + e) = v;
            }
        }
    }
}

// ---------------------------------------------------------------------------
// Tensor-core attention: one block per (b,n,h), 8 warps as
// 4 row-groups (wm: 48 rows) x 2 s-halves (wg: 96 cols).
//   S = Q.K^T single-pass fp16 (Q pre-scaled 1/8)
//   softmax fp32 on fragments, Z deferred ; O = E.V fp16
// ---------------------------------------------------------------------------
#define SQ16  0
#define SK16  24576
#define SVH   49152
#define SOBUF 73728
#define SPMAX 125952
#define SPSUM 127488
#define ATTN_SMEM 129024

__global__ __launch_bounds__(256, 1) void attn_kernel() {
    extern __shared__ char smc[];
    const uint32_t sb = smem_u32(smc);
    const int bid = blockIdx.x;           // ((b*N+n)*H+h)
    const int h = bid & 7;
    const int n = (bid >> 3) & 63;
    const int b = bid >> 9;
    const int tid = threadIdx.x;
    const int wid = tid >> 5, lane = tid & 31;
    const int wm = wid & 3, wg = wid >> 5 ? 0 : 0; // placeholder (replaced below)
    const int wgrp = wid >> 2;

    const size_t base = (size_t)bid * 12288;   // 192*64

    for (int i = tid; i < 1536; i += 256) {
        int row = i >> 3, c16 = i & 7;
        uint32_t off = swz8(row, c16);
        size_t g = base + (size_t)row * 64 + c16 * 8;
        *(uint4*)(smc + SQ16 + off) = *(const uint4*)(g_Q16 + g);
        *(uint4*)(smc + SK16 + off) = *(const uint4*)(g_K16 + g);
        *(uint4*)(smc + SVH  + off) = *(const uint4*)(g_Vh  + g);
    }
    __syncthreads();

    // ---- S = Q.K^T (single-pass fp16), warp tile 48 x 96 ----
    float sacc[3][12][4];
    #pragma unroll
    for (int mt = 0; mt < 3; mt++)
        #pragma unroll
        for (int nt = 0; nt < 12; nt++)
            #pragma unroll
            for (int j = 0; j < 4; j++) sacc[mt][nt][j] = 0.f;

    const int lr = lane & 15, lc = lane >> 4;
    #pragma unroll
    for (int kt = 0; kt < 4; kt++) {
        int c16 = kt * 2 + lc;
        uint32_t qf[3][4];
        #pragma unroll
        for (int mt = 0; mt < 3; mt++) {
            int row = wm * 48 + mt * 16 + lr;
            ldsm_x4(qf[mt], sb + SQ16 + swz8(row, c16));
        }
        uint32_t bh[12][2];
        #pragma unroll
        for (int ntp = 0; ntp < 6; ntp++) {
            int row = wgrp * 96 + ntp * 16 + lr;
            uint32_t r4[4];
            ldsm_x4(r4, sb + SK16 + swz8(row, c16));
            bh[2*ntp][0] = r4[0]; bh[2*ntp][1] = r4[2];
            bh[2*ntp+1][0] = r4[1]; bh[2*ntp+1][1] = r4[3];
        }
        #pragma unroll
        for (int mt = 0; mt < 3; mt++)
            #pragma unroll
            for (int nt = 0; nt < 12; nt++)
                mma16816h(sacc[mt][nt], qf[mt], bh[nt]);
    }

    // ---- softmax: row stats across the two s-half warps ----
    float* pmax = (float*)(smc + SPMAX);
    float* psum = (float*)(smc + SPSUM);
    const int rbase = wm * 48 + (lane >> 2);

    #pragma unroll
    for (int mt = 0; mt < 3; mt++) {
        float m1 = -1e30f, m2 = -1e30f;
        #pragma unroll
        for (int nt = 0; nt < 12; nt++) {
            m1 = fmaxf(m1, fmaxf(sacc[mt][nt][0], sacc[mt][nt][1]));
            m2 = fmaxf(m2, fmaxf(sacc[mt][nt][2], sacc[mt][nt][3]));
        }
        m1 = fmaxf(m1, __shfl_xor_sync(0xffffffffu, m1, 1));
        m1 = fmaxf(m1, __shfl_xor_sync(0xffffffffu, m1, 2));
        m2 = fmaxf(m2, __shfl_xor_sync(0xffffffffu, m2, 1));
        m2 = fmaxf(m2, __shfl_xor_sync(0xffffffffu, m2, 2));
        if ((lane & 3) == 0) {
            pmax[wgrp * 192 + rbase + mt * 16]     = m1;
            pmax[wgrp * 192 + rbase + mt * 16 + 8] = m2;
        }
    }
    __syncthreads();

    uint32_t eh[3][6][4];
    #pragma unroll
    for (int mt = 0; mt < 3; mt++) {
        int rr = rbase + mt * 16;
        float gm1 = fmaxf(pmax[rr],     pmax[192 + rr]);
        float gm2 = fmaxf(pmax[rr + 8], pmax[192 + rr + 8]);
        float s1 = 0.f, s2 = 0.f;
        #pragma unroll
        for (int nt = 0; nt < 12; nt++) {
            float c0 = __expf(sacc[mt][nt][0] - gm1);
            float c1 = __expf(sacc[mt][nt][1] - gm1);
            float c2 = __expf(sacc[mt][nt][2] - gm2);
            float c3 = __expf(sacc[mt][nt][3] - gm2);
            sacc[mt][nt][0] = c0; sacc[mt][nt][1] = c1;
            sacc[mt][nt][2] = c2; sacc[mt][nt][3] = c3;
            s1 += c0 + c1; s2 += c2 + c3;
        }
        s1 += __shfl_xor_sync(0xffffffffu, s1, 1);
        s1 += __shfl_xor_sync(0xffffffffu, s1, 2);
        s2 += __shfl_xor_sync(0xffffffffu, s2, 1);
        s2 += __shfl_xor_sync(0xffffffffu, s2, 2);
        if ((lane & 3) == 0) {
            psum[wgrp * 192 + rr]     = s1;
            psum[wgrp * 192 + rr + 8] = s2;
        }
        #pragma unroll
        for (int ktp = 0; ktp < 6; ktp++) {
            __half2 p;
            p = __floats2half2_rn(sacc[mt][2*ktp][0],   sacc[mt][2*ktp][1]);
            eh[mt][ktp][0] = *(uint32_t*)&p;
            p = __floats2half2_rn(sacc[mt][2*ktp][2],   sacc[mt][2*ktp][3]);
            eh[mt][ktp][1] = *(uint32_t*)&p;
            p = __floats2half2_rn(sacc[mt][2*ktp+1][0], sacc[mt][2*ktp+1][1]);
            eh[mt][ktp][2] = *(uint32_t*)&p;
            p = __floats2half2_rn(sacc[mt][2*ktp+1][2], sacc[mt][2*ktp+1][3]);
            eh[mt][ktp][3] = *(uint32_t*)&p;
        }
    }
    __syncthreads();

    // ---- O_partial = E.V over this warp's 96 s-columns (fp16 mma) ----
    float oacc[3][8][4];
    #pragma unroll
    for (int mt = 0; mt < 3; mt++)
        #pragma unroll
        for (int nt = 0; nt < 8; nt++)
            #pragma unroll
            for (int j = 0; j < 4; j++) oacc[mt][nt][j] = 0.f;

    const int lg = lane >> 3, lr8 = lane & 7;
    #pragma unroll
    for (int ktp = 0; ktp < 6; ktp++) {
        int s0 = wgrp * 96 + ktp * 16;
        int vrow = s0 + lr8 + ((lg & 1) << 3);
        uint32_t bv[8][2];
        #pragma unroll
        for (int np = 0; np < 4; np++) {
            int vc = np * 2 + (lg >> 1);
            uint32_t r4[4];
            ldsm_x4_t(r4, sb + SVH + swz8(vrow, vc));
            bv[2*np][0] = r4[0];   bv[2*np][1] = r4[1];
            bv[2*np+1][0] = r4[2]; bv[2*np+1][1] = r4[3];
        }
        #pragma unroll
        for (int mt = 0; mt < 3; mt++)
            #pragma unroll
            for (int nt = 0; nt < 8; nt++)
                mma16816h(oacc[mt][nt], eh[mt][ktp], bv[nt]);
    }

    // ---- combine s-half partials, normalize by Z, write fp16 ----
    float* obuf = (float*)(smc + SOBUF);   // [192][68]
    if (wgrp == 0) {
        #pragma unroll
        for (int mt = 0; mt < 3; mt++) {
            int rr = rbase + mt * 16;
            #pragma unroll
            for (int nt = 0; nt < 8; nt++) {
                int c = nt * 8 + 2 * (lane & 3);
                *(float2*)&obuf[rr * 68 + c] =
                    make_float2(oacc[mt][nt][0], oacc[mt][nt][1]);
                *(float2*)&obuf[(rr + 8) * 68 + c] =
                    make_float2(oacc[mt][nt][2], oacc[mt][nt][3]);
            }
        }
    }
    __syncthreads();
    if (wgrp == 1) {
        #pragma unroll
        for (int mt = 0; mt < 3; mt++) {
            int rr = rbase + mt * 16;
            float z1 = 1.0f / (psum[rr] + psum[192 + rr]);
            float z2 = 1.0f / (psum[rr + 8] + psum[192 + rr + 8]);
            #pragma unroll
            for (int nt = 0; nt < 8; nt++) {
                int c = nt * 8 + 2 * (lane & 3);
                float2 p1 = *(float2*)&obuf[rr * 68 + c];
                p1.x = (p1.x + oacc[mt][nt][0]) * z1;
                p1.y = (p1.y + oacc[mt][nt][1]) * z1;
                *(float2*)&obuf[rr * 68 + c] = p1;
                float2 p2 = *(float2*)&obuf[(rr + 8) * 68 + c];
                p2.x = (p2.x + oacc[mt][nt][2]) * z2;
                p2.y = (p2.y + oacc[mt][nt][3]) * z2;
                *(float2*)&obuf[(rr + 8) * 68 + c] = p2;
            }
        }
    }
    __syncthreads();

    // coalesced fp16 writeout to [B,T,N,D]
    const size_t obase = (((size_t)b * 192) * 64 + n) * 512 + h * 64;
    for (int i = tid; i < 3072; i += 256) {
        int row = i >> 4, d = (i & 15) * 4;
        float4 v = *(float4*)&obuf[row * 68 + d];
        __half2 p0 = __floats2half2_rn(v.x, v.y);
        __half2 p1 = __floats2half2_rn(v.z, v.w);
        uint2 u; u.x = *(uint32_t*)&p0; u.y = *(uint32_t*)&p1;
        *(uint2*)(g_O16 + obase + (size_t)row * 32768 + d) = u;
    }
}

// ---------------------------------------------------------------------------
extern "C" void kernel_launch(void* const* d_in, const int* in_sizes, int n_in,
                              void* d_out, int out_size) {
    (void)in_sizes; (void)n_in; (void)out_size;
    const float* x    = (const float*)d_in[0];
    const float* Wq_w = (const float*)d_in[1];
    const float* Wq_b = (const float*)d_in[2];
    const float* Wv_w = (const float*)d_in[3];
    const float* Wv_b = (const float*)d_in[4];
    const float* Wk   = (const float*)d_in[5];
    const float* bk   = (const float*)d_in[6];
    const float* Pw   = (const float*)d_in[7];
    const float* Pb   = (const float*)d_in[8];
    const void*  cid  = d_in[9];
    float* out = (float*)d_out;

    cudaFuncSetAttribute(attn_kernel, cudaFuncAttributeMaxDynamicSharedMemorySize,
                         ATTN_SMEM);
    cudaFuncSetAttribute(qkv_gemm, cudaFuncAttributeMaxDynamicSharedMemorySize,
                         GEMM_SMEM);
    cudaFuncSetAttribute(proj_gemm, cudaFuncAttributeMaxDynamicSharedMemorySize,
                         GEMM_SMEM);

    cid_kernel<<<1, 64>>>(cid);
    conv_x16<<<49152, 256>>>(x, 12582912);
    conv_wkT<<<dim3(16, 16, 8), dim3(32, 32)>>>(Wk);
    conv_w16<<<256, 256>>>(Wq_w, 1, 65536);
    conv_w16<<<256, 256>>>(Wv_w, 2, 65536);
    qkv_gemm<<<dim3(12, 12, 64), 256, GEMM_SMEM>>>(Wq_b, Wv_b, bk);
    attn_kernel<<<4096, 256, ATTN_SMEM>>>();
    conv_w16<<<256, 256>>>(Pw, 3, 65536);
    proj_gemm<<<dim3(4, 768), 256, GEMM_SMEM>>>(Pb, out);
}